// round 1
// baseline (speedup 1.0000x reference)
#include <cuda_runtime.h>
#include <math.h>

#define BATCH 2
#define NTOK  2048
#define HEADS 24
#define DHEAD 128
#define CM    3072
#define MTOT  (BATCH*NTOK)   // 4096

// Scratch (device globals are the sanctioned no-alloc workaround).
// 16B+ alignment required for float4 access.
__device__ __align__(256) float g_q[(size_t)BATCH*HEADS*NTOK*DHEAD];
__device__ __align__(256) float g_k[(size_t)BATCH*HEADS*NTOK*DHEAD];
__device__ __align__(256) float g_v[(size_t)BATCH*HEADS*NTOK*DHEAD];
__device__ __align__(256) float g_att[(size_t)MTOT*CM];

// ---------------------------------------------------------------------------
// SGEMM-NT: C[m,n] = sum_k A[m,k]*B[n,k] + bias[n]
// Both A and B row-major with K contiguous (A@W^T pattern).
// 128x128 tile, BK=16, 256 threads, 8x8 per-thread microtile.
// MODE 0: write C row-major [M,N].
// MODE 1: scatter into g_q/g_k/g_v as [B,H,N,D] (n-tile == exactly one head).
// ---------------------------------------------------------------------------
template<int MODE>
__global__ __launch_bounds__(256, 2)
void sgemm_nt(const float* __restrict__ A, const float* __restrict__ B,
              const float* __restrict__ bias, float* __restrict__ C,
              int M, int N, int K)
{
    __shared__ float As[16][132];   // [k][m], pad 132 to break transpose-store conflicts
    __shared__ float Bs[16][132];   // [k][n]

    const int tid = threadIdx.x;
    const int tx = tid & 15, ty = tid >> 4;
    const int m0 = blockIdx.y * 128;
    const int n0 = blockIdx.x * 128;

    float acc[8][8];
    #pragma unroll
    for (int i = 0; i < 8; ++i)
        #pragma unroll
        for (int j = 0; j < 8; ++j) acc[i][j] = 0.f;

    const float* Ap = A + (size_t)m0 * K;
    const float* Bp = B + (size_t)n0 * K;

    for (int k0 = 0; k0 < K; k0 += 16) {
        #pragma unroll
        for (int it = 0; it < 2; ++it) {
            int lin = it * 256 + tid;        // [0,512): 128 rows x 4 float4
            int r  = lin >> 2;
            int kq = lin & 3;
            float4 a = *(const float4*)(Ap + (size_t)r * K + k0 + kq * 4);
            As[kq*4+0][r] = a.x; As[kq*4+1][r] = a.y;
            As[kq*4+2][r] = a.z; As[kq*4+3][r] = a.w;
            float4 b = *(const float4*)(Bp + (size_t)r * K + k0 + kq * 4);
            Bs[kq*4+0][r] = b.x; Bs[kq*4+1][r] = b.y;
            Bs[kq*4+2][r] = b.z; Bs[kq*4+3][r] = b.w;
        }
        __syncthreads();

        #pragma unroll
        for (int kk = 0; kk < 16; ++kk) {
            float ar[8], br[8];
            *(float4*)&ar[0] = *(const float4*)&As[kk][ty*4];
            *(float4*)&ar[4] = *(const float4*)&As[kk][64 + ty*4];
            *(float4*)&br[0] = *(const float4*)&Bs[kk][tx*4];
            *(float4*)&br[4] = *(const float4*)&Bs[kk][64 + tx*4];
            #pragma unroll
            for (int i = 0; i < 8; ++i)
                #pragma unroll
                for (int j = 0; j < 8; ++j)
                    acc[i][j] = fmaf(ar[i], br[j], acc[i][j]);
        }
        __syncthreads();
    }

    // bias per column of this thread
    float bj[8];
    #pragma unroll
    for (int j = 0; j < 8; ++j) {
        int nc = n0 + ((j < 4) ? (tx*4 + j) : (64 + tx*4 + (j - 4)));
        bj[j] = bias[nc];
    }

    if (MODE == 0) {
        #pragma unroll
        for (int i = 0; i < 8; ++i) {
            int m = m0 + ((i < 4) ? (ty*4 + i) : (64 + ty*4 + (i - 4)));
            float4 v0 = make_float4(acc[i][0]+bj[0], acc[i][1]+bj[1],
                                    acc[i][2]+bj[2], acc[i][3]+bj[3]);
            float4 v1 = make_float4(acc[i][4]+bj[4], acc[i][5]+bj[5],
                                    acc[i][6]+bj[6], acc[i][7]+bj[7]);
            float* Crow = C + (size_t)m * N + n0;
            *(float4*)(Crow + tx*4)      = v0;
            *(float4*)(Crow + 64 + tx*4) = v1;
        }
    } else {
        // Tile n-range [n0, n0+128) maps to exactly one (part, head); d = local col.
        int part = n0 / CM;
        int head = (n0 % CM) >> 7;
        float* dst = (part == 0) ? g_q : ((part == 1) ? g_k : g_v);
        #pragma unroll
        for (int i = 0; i < 8; ++i) {
            int m   = m0 + ((i < 4) ? (ty*4 + i) : (64 + ty*4 + (i - 4)));
            int b   = m >> 11;          // /2048
            int tok = m & (NTOK - 1);
            size_t rb = (((size_t)b * HEADS + head) * NTOK + tok) * DHEAD;
            float4 v0 = make_float4(acc[i][0]+bj[0], acc[i][1]+bj[1],
                                    acc[i][2]+bj[2], acc[i][3]+bj[3]);
            float4 v1 = make_float4(acc[i][4]+bj[4], acc[i][5]+bj[5],
                                    acc[i][6]+bj[6], acc[i][7]+bj[7]);
            *(float4*)(dst + rb + tx*4)      = v0;
            *(float4*)(dst + rb + 64 + tx*4) = v1;
        }
    }
}

// ---------------------------------------------------------------------------
// Fused RMSNorm + 3D RoPE over one (b,h,tok) row of D=128.
// grid.x = B*H*NTOK, grid.y = 2 (0 -> q, 1 -> k), 128 threads.
// head_dim=128 -> dim_t=44, dim_h=dim_w=42. n = t*256 + h*16 + w.
// rotate_half: even d -> -x[d+1], odd d -> x[d-1].
// ---------------------------------------------------------------------------
__global__ void rope_rms_kernel(const float* __restrict__ qn_w,
                                const float* __restrict__ kn_w)
{
    const int row = blockIdx.x;
    const int d   = threadIdx.x;
    float* buf       = (blockIdx.y == 0) ? g_q : g_k;
    const float* w   = (blockIdx.y == 0) ? qn_w : kn_w;
    const int tok = row & (NTOK - 1);

    float x = buf[(size_t)row * DHEAD + d];

    __shared__ float sred[4];
    __shared__ float sh[128];
    float v = x * x;
    #pragma unroll
    for (int o = 16; o; o >>= 1) v += __shfl_xor_sync(0xffffffffu, v, o);
    if ((d & 31) == 0) sred[d >> 5] = v;
    __syncthreads();
    float ss = sred[0] + sred[1] + sred[2] + sred[3];
    float y  = x * rsqrtf(ss * (1.f / DHEAD) + 1e-6f) * w[d];
    sh[d] = y;
    __syncthreads();
    float rot = (d & 1) ? sh[d - 1] : -sh[d + 1];

    float pos, e;
    if (d < 44)      { pos = (float)(tok >> 8);        e = (float)(d & ~1)        * (1.f / 44.f); }
    else if (d < 86) { pos = (float)((tok >> 4) & 15); e = (float)((d - 44) & ~1) * (1.f / 42.f); }
    else             { pos = (float)(tok & 15);        e = (float)((d - 86) & ~1) * (1.f / 42.f); }
    float f = expf(-9.210340371976184f * e);   // 10000^{-e}
    float ang = pos * f;
    float cs, sn;
    sincosf(ang, &sn, &cs);
    buf[(size_t)row * DHEAD + d] = y * cs + rot * sn;
}

// ---------------------------------------------------------------------------
// Flash attention, fp32. One block per (64 q-rows, head, batch).
// Streams K/V in 64-row chunks; online softmax; O in registers.
// 256 threads as 16x16: thread owns 4 q-rows x 4 k-cols (S) and 4 q x 8 d (O).
// smem (dynamic, 92160 B):
//   Qts [128][72]  (d-major, pre-scaled by 1/sqrt(D))
//   Kts [128][72]  (d-major)  -- reused as Vs [64][128] for the PV phase
//   Pt  [64][72]   (kc-major)
// ---------------------------------------------------------------------------
__global__ __launch_bounds__(256, 2)
void flash_kernel(float* __restrict__ att)
{
    extern __shared__ float sm[];
    float* Qts = sm;                    // 128*72 floats
    float* Kts = sm + 128 * 72;         // 128*72 floats (union Vs 64*128)
    float* Pt  = sm + 2 * 128 * 72;     // 64*72 floats

    const int tid = threadIdx.x;
    const int tx = tid & 15, ty = tid >> 4;
    const int q0 = blockIdx.x * 64;
    const size_t hb = ((size_t)blockIdx.z * HEADS + blockIdx.y) * NTOK * DHEAD;
    const float* Q  = g_q + hb + (size_t)q0 * DHEAD;
    const float* Kp = g_k + hb;
    const float* Vp = g_v + hb;
    const float sc = 0.08838834764831845f;  // 128^-0.5

    for (int idx = tid; idx < 64 * 128; idx += 256) {
        int r = idx >> 7, d = idx & 127;
        Qts[d * 72 + r] = Q[idx] * sc;
    }

    float o[4][8];
    #pragma unroll
    for (int i = 0; i < 4; ++i)
        #pragma unroll
        for (int j = 0; j < 8; ++j) o[i][j] = 0.f;
    float mrow[4] = {-INFINITY, -INFINITY, -INFINITY, -INFINITY};
    float lrow[4] = {0.f, 0.f, 0.f, 0.f};

    __syncthreads();

    for (int c0 = 0; c0 < NTOK; c0 += 64) {
        // K chunk, transposed to d-major
        for (int idx = tid; idx < 64 * 128; idx += 256) {
            int r = idx >> 7, d = idx & 127;
            Kts[d * 72 + r] = Kp[(size_t)(c0 + r) * DHEAD + d];
        }
        __syncthreads();

        // S = (Q*sc) . K^T  (4x4 per thread)
        float s4[4][4];
        #pragma unroll
        for (int i = 0; i < 4; ++i)
            #pragma unroll
            for (int j = 0; j < 4; ++j) s4[i][j] = 0.f;

        #pragma unroll 4
        for (int kd = 0; kd < 128; ++kd) {
            float4 aq = *(const float4*)&Qts[kd * 72 + ty * 4];
            float4 bk = *(const float4*)&Kts[kd * 72 + tx * 4];
            float ar[4] = {aq.x, aq.y, aq.z, aq.w};
            float br[4] = {bk.x, bk.y, bk.z, bk.w};
            #pragma unroll
            for (int i = 0; i < 4; ++i)
                #pragma unroll
                for (int j = 0; j < 4; ++j)
                    s4[i][j] = fmaf(ar[i], br[j], s4[i][j]);
        }

        // online softmax; rows of a given ty live in one 16-lane shfl group
        #pragma unroll
        for (int i = 0; i < 4; ++i) {
            float mc = fmaxf(fmaxf(s4[i][0], s4[i][1]), fmaxf(s4[i][2], s4[i][3]));
            #pragma unroll
            for (int off = 8; off; off >>= 1)
                mc = fmaxf(mc, __shfl_xor_sync(0xffffffffu, mc, off));
            float mn = fmaxf(mrow[i], mc);
            float alpha = __expf(mrow[i] - mn);
            mrow[i] = mn;
            float rs = 0.f;
            #pragma unroll
            for (int j = 0; j < 4; ++j) {
                float p = __expf(s4[i][j] - mn);
                s4[i][j] = p;
                rs += p;
            }
            #pragma unroll
            for (int off = 8; off; off >>= 1)
                rs += __shfl_xor_sync(0xffffffffu, rs, off);
            lrow[i] = lrow[i] * alpha + rs;
            #pragma unroll
            for (int jj = 0; jj < 8; ++jj) o[i][jj] *= alpha;
            #pragma unroll
            for (int j = 0; j < 4; ++j)
                Pt[(tx * 4 + j) * 72 + ty * 4 + i] = s4[i][j];
        }
        __syncthreads();   // Kts reads + Pt writes done

        // V chunk into the Kts footprint, natural [kc][d] layout
        float* Vs = Kts;
        for (int idx = tid; idx < 64 * 128; idx += 256)
            Vs[idx] = Vp[(size_t)c0 * DHEAD + idx];
        __syncthreads();

        // O += P . V
        #pragma unroll 2
        for (int kc = 0; kc < 64; ++kc) {
            float4 p  = *(const float4*)&Pt[kc * 72 + ty * 4];
            float4 v0 = *(const float4*)&Vs[kc * 128 + tx * 8];
            float4 v1 = *(const float4*)&Vs[kc * 128 + tx * 8 + 4];
            float pr[4] = {p.x, p.y, p.z, p.w};
            #pragma unroll
            for (int i = 0; i < 4; ++i) {
                o[i][0] = fmaf(pr[i], v0.x, o[i][0]);
                o[i][1] = fmaf(pr[i], v0.y, o[i][1]);
                o[i][2] = fmaf(pr[i], v0.z, o[i][2]);
                o[i][3] = fmaf(pr[i], v0.w, o[i][3]);
                o[i][4] = fmaf(pr[i], v1.x, o[i][4]);
                o[i][5] = fmaf(pr[i], v1.y, o[i][5]);
                o[i][6] = fmaf(pr[i], v1.z, o[i][6]);
                o[i][7] = fmaf(pr[i], v1.w, o[i][7]);
            }
        }
        __syncthreads();   // before next chunk overwrites Vs/Pt
    }

    // normalize + write [B, N, H, D]
    #pragma unroll
    for (int i = 0; i < 4; ++i) {
        float inv = 1.f / lrow[i];
        int qr = q0 + ty * 4 + i;
        size_t ob = (((size_t)blockIdx.z * NTOK + qr) * HEADS + blockIdx.y) * DHEAD
                    + tx * 8;
        float4 w0 = make_float4(o[i][0]*inv, o[i][1]*inv, o[i][2]*inv, o[i][3]*inv);
        float4 w1 = make_float4(o[i][4]*inv, o[i][5]*inv, o[i][6]*inv, o[i][7]*inv);
        *(float4*)(att + ob)     = w0;
        *(float4*)(att + ob + 4) = w1;
    }
}

// ---------------------------------------------------------------------------
extern "C" void kernel_launch(void* const* d_in, const int* in_sizes, int n_in,
                              void* d_out, int out_size)
{
    const float* x      = (const float*)d_in[0];
    const float* qkv_w  = (const float*)d_in[1];
    const float* qkv_b  = (const float*)d_in[2];
    const float* qn_w   = (const float*)d_in[3];
    const float* kn_w   = (const float*)d_in[4];
    const float* proj_w = (const float*)d_in[5];
    const float* proj_b = (const float*)d_in[6];
    float* out = (float*)d_out;

    float* att_ptr = nullptr;
    cudaGetSymbolAddress((void**)&att_ptr, g_att);

    // 1) QKV GEMM + bias, scattered into per-head q/k/v layouts
    sgemm_nt<1><<<dim3((3 * CM) / 128, MTOT / 128), 256>>>(
        x, qkv_w, qkv_b, nullptr, MTOT, 3 * CM, CM);

    // 2) RMSNorm + 3D RoPE on q and k
    rope_rms_kernel<<<dim3(BATCH * HEADS * NTOK, 2), 128>>>(qn_w, kn_w);

    // 3) Flash attention
    cudaFuncSetAttribute(flash_kernel,
                         cudaFuncAttributeMaxDynamicSharedMemorySize, 92160);
    flash_kernel<<<dim3(NTOK / 64, HEADS, BATCH), 256, 92160>>>(att_ptr);

    // 4) Output projection + bias
    sgemm_nt<0><<<dim3(CM / 128, MTOT / 128), 256>>>(
        att_ptr, proj_w, proj_b, out, MTOT, CM, CM);
}

// round 2
// speedup vs baseline: 3.1693x; 3.1693x over previous
#include <cuda_runtime.h>
#include <math.h>
#include <stdint.h>

#define BATCH 2
#define NTOK  2048
#define HEADS 24
#define DHEAD 128
#define CM    3072
#define MTOT  (BATCH*NTOK)   // 4096

__device__ __align__(256) float g_q[(size_t)BATCH*HEADS*NTOK*DHEAD];
__device__ __align__(256) float g_k[(size_t)BATCH*HEADS*NTOK*DHEAD];
__device__ __align__(256) float g_v[(size_t)BATCH*HEADS*NTOK*DHEAD];
__device__ __align__(256) float g_att[(size_t)MTOT*CM];

__device__ __forceinline__ uint32_t f2tf(float f) {
    uint32_t u;
    asm("cvt.rna.tf32.f32 %0, %1;" : "=r"(u) : "f"(f));
    return u;
}

__device__ __forceinline__ void mma8(float c[4], const uint32_t a[4], const uint32_t b[2]) {
    asm("mma.sync.aligned.m16n8k8.row.col.f32.tf32.tf32.f32 "
        "{%0,%1,%2,%3},{%4,%5,%6,%7},{%8,%9},{%0,%1,%2,%3};"
        : "+f"(c[0]), "+f"(c[1]), "+f"(c[2]), "+f"(c[3])
        : "r"(a[0]), "r"(a[1]), "r"(a[2]), "r"(a[3]), "r"(b[0]), "r"(b[1]));
}

// ---------------------------------------------------------------------------
// tf32 MMA GEMM-NT: C[m,n] = sum_k A[m,k]*B[n,k] + bias[n]
// 128x128 block, 256 thr (8 warps as 2m x 4n), warp tile 64x32, BK=16.
// smem row stride 20 -> conflict-free per-lane fragment LDS.
// MODE 0: row-major C.  MODE 1: scatter to g_q/g_k/g_v [B,H,N,D].
// ---------------------------------------------------------------------------
template<int MODE>
__global__ __launch_bounds__(256, 2)
void gemm_mma(const float* __restrict__ A, const float* __restrict__ B,
              const float* __restrict__ bias, float* __restrict__ C,
              int M, int N, int K)
{
    __shared__ float As[128 * 20];
    __shared__ float Bs[128 * 20];

    const int tid  = threadIdx.x;
    const int lane = tid & 31, warp = tid >> 5;
    const int g = lane >> 2, cq = lane & 3;
    const int wm = warp >> 2, wn = warp & 3;     // 2 x 4 warp grid
    const int m0 = blockIdx.x * 128, n0 = blockIdx.y * 128;

    float acc[4][4][4] = {};

    const int lr = tid >> 2;   // 0..63
    const int lq = tid & 3;    // float4 slot within a BK=16 row
    const float* Ag = A + (size_t)(m0 + lr) * K + lq * 4;
    const float* Bg = B + (size_t)(n0 + lr) * K + lq * 4;

    float4 pa0, pa1, pb0, pb1;
    pa0 = *(const float4*)(Ag);
    pa1 = *(const float4*)(Ag + (size_t)64 * K);
    pb0 = *(const float4*)(Bg);
    pb1 = *(const float4*)(Bg + (size_t)64 * K);

    {
        uint4 u;
        u = make_uint4(f2tf(pa0.x), f2tf(pa0.y), f2tf(pa0.z), f2tf(pa0.w));
        *(uint4*)&As[lr * 20 + lq * 4] = u;
        u = make_uint4(f2tf(pa1.x), f2tf(pa1.y), f2tf(pa1.z), f2tf(pa1.w));
        *(uint4*)&As[(lr + 64) * 20 + lq * 4] = u;
        u = make_uint4(f2tf(pb0.x), f2tf(pb0.y), f2tf(pb0.z), f2tf(pb0.w));
        *(uint4*)&Bs[lr * 20 + lq * 4] = u;
        u = make_uint4(f2tf(pb1.x), f2tf(pb1.y), f2tf(pb1.z), f2tf(pb1.w));
        *(uint4*)&Bs[(lr + 64) * 20 + lq * 4] = u;
    }
    __syncthreads();

    for (int k0 = 0; k0 < K; k0 += 16) {
        const bool more = (k0 + 16) < K;
        if (more) {
            pa0 = *(const float4*)(Ag + k0 + 16);
            pa1 = *(const float4*)(Ag + (size_t)64 * K + k0 + 16);
            pb0 = *(const float4*)(Bg + k0 + 16);
            pb1 = *(const float4*)(Bg + (size_t)64 * K + k0 + 16);
        }

        #pragma unroll
        for (int kk = 0; kk < 2; ++kk) {
            uint32_t af[4][4], bf[4][2];
            #pragma unroll
            for (int mt = 0; mt < 4; ++mt) {
                int row = wm * 64 + mt * 16 + g;
                af[mt][0] = __float_as_uint(As[row * 20 + kk * 8 + cq]);
                af[mt][1] = __float_as_uint(As[(row + 8) * 20 + kk * 8 + cq]);
                af[mt][2] = __float_as_uint(As[row * 20 + kk * 8 + cq + 4]);
                af[mt][3] = __float_as_uint(As[(row + 8) * 20 + kk * 8 + cq + 4]);
            }
            #pragma unroll
            for (int nt = 0; nt < 4; ++nt) {
                int colr = wn * 32 + nt * 8 + g;
                bf[nt][0] = __float_as_uint(Bs[colr * 20 + kk * 8 + cq]);
                bf[nt][1] = __float_as_uint(Bs[colr * 20 + kk * 8 + cq + 4]);
            }
            #pragma unroll
            for (int mt = 0; mt < 4; ++mt)
                #pragma unroll
                for (int nt = 0; nt < 4; ++nt)
                    mma8(acc[mt][nt], af[mt], bf[nt]);
        }
        __syncthreads();
        if (more) {
            uint4 u;
            u = make_uint4(f2tf(pa0.x), f2tf(pa0.y), f2tf(pa0.z), f2tf(pa0.w));
            *(uint4*)&As[lr * 20 + lq * 4] = u;
            u = make_uint4(f2tf(pa1.x), f2tf(pa1.y), f2tf(pa1.z), f2tf(pa1.w));
            *(uint4*)&As[(lr + 64) * 20 + lq * 4] = u;
            u = make_uint4(f2tf(pb0.x), f2tf(pb0.y), f2tf(pb0.z), f2tf(pb0.w));
            *(uint4*)&Bs[lr * 20 + lq * 4] = u;
            u = make_uint4(f2tf(pb1.x), f2tf(pb1.y), f2tf(pb1.z), f2tf(pb1.w));
            *(uint4*)&Bs[(lr + 64) * 20 + lq * 4] = u;
            __syncthreads();
        }
    }

    // Epilogue. acc layout: c0=[r][2j], c1=[r][2j+1], c2=[r+8][2j], c3=[r+8][2j+1]
    #pragma unroll
    for (int mt = 0; mt < 4; ++mt) {
        int r0 = m0 + wm * 64 + mt * 16 + g;
        int r1 = r0 + 8;
        #pragma unroll
        for (int nt = 0; nt < 4; ++nt) {
            int col = n0 + wn * 32 + nt * 8 + 2 * cq;
            float b0 = bias[col], b1 = bias[col + 1];
            float2 v0 = make_float2(acc[mt][nt][0] + b0, acc[mt][nt][1] + b1);
            float2 v1 = make_float2(acc[mt][nt][2] + b0, acc[mt][nt][3] + b1);
            if (MODE == 0) {
                *(float2*)(C + (size_t)r0 * N + col) = v0;
                *(float2*)(C + (size_t)r1 * N + col) = v1;
            } else {
                int part = col / CM;
                int within = col % CM;
                int head = within >> 7;
                int d = within & 127;
                float* dst = (part == 0) ? g_q : ((part == 1) ? g_k : g_v);
                int b0i = r0 >> 11, t0 = r0 & (NTOK - 1);
                int b1i = r1 >> 11, t1 = r1 & (NTOK - 1);
                *(float2*)(dst + (((size_t)b0i * HEADS + head) * NTOK + t0) * DHEAD + d) = v0;
                *(float2*)(dst + (((size_t)b1i * HEADS + head) * NTOK + t1) * DHEAD + d) = v1;
            }
        }
    }
}

// ---------------------------------------------------------------------------
// Fused RMSNorm + 3D RoPE (unchanged from round 1 — correct, tiny cost).
// ---------------------------------------------------------------------------
__global__ void rope_rms_kernel(const float* __restrict__ qn_w,
                                const float* __restrict__ kn_w)
{
    const int row = blockIdx.x;
    const int d   = threadIdx.x;
    float* buf     = (blockIdx.y == 0) ? g_q : g_k;
    const float* w = (blockIdx.y == 0) ? qn_w : kn_w;
    const int tok = row & (NTOK - 1);

    float x = buf[(size_t)row * DHEAD + d];

    __shared__ float sred[4];
    __shared__ float sh[128];
    float v = x * x;
    #pragma unroll
    for (int o = 16; o; o >>= 1) v += __shfl_xor_sync(0xffffffffu, v, o);
    if ((d & 31) == 0) sred[d >> 5] = v;
    __syncthreads();
    float ss = sred[0] + sred[1] + sred[2] + sred[3];
    float y  = x * rsqrtf(ss * (1.f / DHEAD) + 1e-6f) * w[d];
    sh[d] = y;
    __syncthreads();
    float rot = (d & 1) ? sh[d - 1] : -sh[d + 1];

    float pos, e;
    if (d < 44)      { pos = (float)(tok >> 8);        e = (float)(d & ~1)        * (1.f / 44.f); }
    else if (d < 86) { pos = (float)((tok >> 4) & 15); e = (float)((d - 44) & ~1) * (1.f / 42.f); }
    else             { pos = (float)(tok & 15);        e = (float)((d - 86) & ~1) * (1.f / 42.f); }
    float f = expf(-9.210340371976184f * e);
    float ang = pos * f;
    float cs, sn;
    sincosf(ang, &sn, &cs);
    buf[(size_t)row * DHEAD + d] = y * cs + rot * sn;
}

// ---------------------------------------------------------------------------
// Flash attention with tf32 MMA.
// Block = 64 q rows, 128 threads (4 warps, 16 rows each). Bc = 64.
// Q fragments register-resident. S-acc is reused directly as the A operand
// of P@V via the k-order permutation (kappa=c <-> kc=2c, kappa=c+4 <-> 2c+1),
// which makes the V B-fragment regs adjacent physical rows -> natural layout.
// smem: Ks[64][132] + Vs[64][132] = 67.6 KB dynamic.
// ---------------------------------------------------------------------------
__global__ __launch_bounds__(128, 2)
void flash_mma(float* __restrict__ att)
{
    extern __shared__ float sm[];
    float* Ks = sm;               // 64*132
    float* Vs = sm + 64 * 132;    // 64*132

    const int tid = threadIdx.x, lane = tid & 31, w = tid >> 5;
    const int g = lane >> 2, cq = lane & 3;
    const int q0 = blockIdx.x * 64;
    const size_t hb = ((size_t)blockIdx.z * HEADS + blockIdx.y) * NTOK * DHEAD;
    const float* Qg = g_q + hb + (size_t)q0 * DHEAD;
    const float* Kg = g_k + hb;
    const float* Vg = g_v + hb;
    const float sc = 0.08838834764831845f;

    // Stage Q (pre-scaled, tf32) through Ks, pull fragments to registers.
    #pragma unroll
    for (int it = 0; it < 16; ++it) {
        int r = it * 4 + w;
        float4 v = *(const float4*)(Qg + (size_t)r * DHEAD + lane * 4);
        uint4 u = make_uint4(f2tf(v.x * sc), f2tf(v.y * sc), f2tf(v.z * sc), f2tf(v.w * sc));
        *(uint4*)&Ks[r * 132 + lane * 4] = u;
    }
    __syncthreads();
    uint32_t qa[16][4];
    {
        int row = w * 16 + g;
        #pragma unroll
        for (int kk = 0; kk < 16; ++kk) {
            qa[kk][0] = __float_as_uint(Ks[row * 132 + kk * 8 + cq]);
            qa[kk][1] = __float_as_uint(Ks[(row + 8) * 132 + kk * 8 + cq]);
            qa[kk][2] = __float_as_uint(Ks[row * 132 + kk * 8 + cq + 4]);
            qa[kk][3] = __float_as_uint(Ks[(row + 8) * 132 + kk * 8 + cq + 4]);
        }
    }
    __syncthreads();

    float od[16][4] = {};
    float m0 = -INFINITY, m1 = -INFINITY, l0 = 0.f, l1 = 0.f;

    for (int c0 = 0; c0 < NTOK; c0 += 64) {
        // K and V chunks (tf32 at store)
        #pragma unroll
        for (int it = 0; it < 16; ++it) {
            int r = it * 4 + w;
            float4 kv = *(const float4*)(Kg + (size_t)(c0 + r) * DHEAD + lane * 4);
            uint4 uk = make_uint4(f2tf(kv.x), f2tf(kv.y), f2tf(kv.z), f2tf(kv.w));
            *(uint4*)&Ks[r * 132 + lane * 4] = uk;
            float4 vv = *(const float4*)(Vg + (size_t)(c0 + r) * DHEAD + lane * 4);
            uint4 uv = make_uint4(f2tf(vv.x), f2tf(vv.y), f2tf(vv.z), f2tf(vv.w));
            *(uint4*)&Vs[r * 132 + lane * 4] = uv;
        }
        __syncthreads();

        // S = Q.K^T : warp rows w*16.., cols 0..63 (8 n-tiles)
        float s[8][4] = {};
        #pragma unroll
        for (int kk = 0; kk < 16; ++kk) {
            #pragma unroll
            for (int nt = 0; nt < 8; ++nt) {
                uint32_t b[2];
                int key = nt * 8 + g;
                b[0] = __float_as_uint(Ks[key * 132 + kk * 8 + cq]);
                b[1] = __float_as_uint(Ks[key * 132 + kk * 8 + cq + 4]);
                mma8(s[nt], qa[kk], b);
            }
        }

        // Online softmax. Row r=w*16+g -> s[nt][0,1]; row r+8 -> s[nt][2,3].
        float cm0 = -INFINITY, cm1 = -INFINITY;
        #pragma unroll
        for (int nt = 0; nt < 8; ++nt) {
            cm0 = fmaxf(cm0, fmaxf(s[nt][0], s[nt][1]));
            cm1 = fmaxf(cm1, fmaxf(s[nt][2], s[nt][3]));
        }
        cm0 = fmaxf(cm0, __shfl_xor_sync(0xffffffffu, cm0, 1));
        cm0 = fmaxf(cm0, __shfl_xor_sync(0xffffffffu, cm0, 2));
        cm1 = fmaxf(cm1, __shfl_xor_sync(0xffffffffu, cm1, 1));
        cm1 = fmaxf(cm1, __shfl_xor_sync(0xffffffffu, cm1, 2));
        float mn0 = fmaxf(m0, cm0), mn1 = fmaxf(m1, cm1);
        float al0 = __expf(m0 - mn0), al1 = __expf(m1 - mn1);
        m0 = mn0; m1 = mn1;

        float rs0 = 0.f, rs1 = 0.f;
        #pragma unroll
        for (int nt = 0; nt < 8; ++nt) {
            s[nt][0] = __expf(s[nt][0] - mn0); rs0 += s[nt][0];
            s[nt][1] = __expf(s[nt][1] - mn0); rs0 += s[nt][1];
            s[nt][2] = __expf(s[nt][2] - mn1); rs1 += s[nt][2];
            s[nt][3] = __expf(s[nt][3] - mn1); rs1 += s[nt][3];
        }
        rs0 += __shfl_xor_sync(0xffffffffu, rs0, 1);
        rs0 += __shfl_xor_sync(0xffffffffu, rs0, 2);
        rs1 += __shfl_xor_sync(0xffffffffu, rs1, 1);
        rs1 += __shfl_xor_sync(0xffffffffu, rs1, 2);
        l0 = l0 * al0 + rs0;
        l1 = l1 * al1 + rs1;

        #pragma unroll
        for (int dt = 0; dt < 16; ++dt) {
            od[dt][0] *= al0; od[dt][1] *= al0;
            od[dt][2] *= al1; od[dt][3] *= al1;
        }

        // P as A fragments: {a0,a1,a2,a3} = {s0, s2, s1, s3} (tf32)
        uint32_t pa[8][4];
        #pragma unroll
        for (int nt = 0; nt < 8; ++nt) {
            pa[nt][0] = f2tf(s[nt][0]);
            pa[nt][1] = f2tf(s[nt][2]);
            pa[nt][2] = f2tf(s[nt][1]);
            pa[nt][3] = f2tf(s[nt][3]);
        }

        // O += P.V : logical k col kappa=c -> physical kc=kk*8+2c, kappa=c+4 -> +2c+1
        #pragma unroll
        for (int kk = 0; kk < 8; ++kk) {
            #pragma unroll
            for (int dt = 0; dt < 16; ++dt) {
                uint32_t b[2];
                b[0] = __float_as_uint(Vs[(kk * 8 + 2 * cq) * 132 + dt * 8 + g]);
                b[1] = __float_as_uint(Vs[(kk * 8 + 2 * cq + 1) * 132 + dt * 8 + g]);
                mma8(od[dt], pa[kk], b);
            }
        }
        __syncthreads();
    }

    // Normalize + write [B, N, H, D]
    float inv0 = 1.f / l0, inv1 = 1.f / l1;
    int r0 = q0 + w * 16 + g, r1 = r0 + 8;
    size_t base0 = (((size_t)blockIdx.z * NTOK + r0) * HEADS + blockIdx.y) * DHEAD;
    size_t base1 = (((size_t)blockIdx.z * NTOK + r1) * HEADS + blockIdx.y) * DHEAD;
    #pragma unroll
    for (int dt = 0; dt < 16; ++dt) {
        int col = dt * 8 + 2 * cq;
        *(float2*)(att + base0 + col) = make_float2(od[dt][0] * inv0, od[dt][1] * inv0);
        *(float2*)(att + base1 + col) = make_float2(od[dt][2] * inv1, od[dt][3] * inv1);
    }
}

// ---------------------------------------------------------------------------
extern "C" void kernel_launch(void* const* d_in, const int* in_sizes, int n_in,
                              void* d_out, int out_size)
{
    const float* x      = (const float*)d_in[0];
    const float* qkv_w  = (const float*)d_in[1];
    const float* qkv_b  = (const float*)d_in[2];
    const float* qn_w   = (const float*)d_in[3];
    const float* kn_w   = (const float*)d_in[4];
    const float* proj_w = (const float*)d_in[5];
    const float* proj_b = (const float*)d_in[6];
    float* out = (float*)d_out;

    float* att_ptr = nullptr;
    cudaGetSymbolAddress((void**)&att_ptr, g_att);

    // 1) QKV GEMM + bias -> scatter to per-head q/k/v
    gemm_mma<1><<<dim3(MTOT / 128, (3 * CM) / 128), 256>>>(
        x, qkv_w, qkv_b, nullptr, MTOT, 3 * CM, CM);

    // 2) RMSNorm + 3D RoPE
    rope_rms_kernel<<<dim3(BATCH * HEADS * NTOK, 2), 128>>>(qn_w, kn_w);

    // 3) Flash attention (tf32 mma)
    cudaFuncSetAttribute(flash_mma,
                         cudaFuncAttributeMaxDynamicSharedMemorySize, 2 * 64 * 132 * 4);
    flash_mma<<<dim3(NTOK / 64, HEADS, BATCH), 128, 2 * 64 * 132 * 4>>>(att_ptr);

    // 4) Output projection
    gemm_mma<0><<<dim3(MTOT / 128, CM / 128), 256>>>(
        att_ptr, proj_w, proj_b, out, MTOT, CM, CM);
}

// round 4
// speedup vs baseline: 6.6218x; 2.0893x over previous
#include <cuda_runtime.h>
#include <cuda_fp16.h>
#include <math.h>
#include <stdint.h>

#define BATCH 2
#define NTOK  2048
#define HEADS 24
#define DHEAD 128
#define CM    3072
#define MTOT  (BATCH*NTOK)   // 4096

// fp32 scratch (q,k pre-rope)
__device__ __align__(256) float g_q[(size_t)BATCH*HEADS*NTOK*DHEAD];
__device__ __align__(256) float g_k[(size_t)BATCH*HEADS*NTOK*DHEAD];
// fp16 scratch
__device__ __align__(256) __half g_x16[(size_t)MTOT*CM];
__device__ __align__(256) __half g_w16[(size_t)3*CM*CM];
__device__ __align__(256) __half g_pw16[(size_t)CM*CM];
__device__ __align__(256) __half g_q16[(size_t)BATCH*HEADS*NTOK*DHEAD];
__device__ __align__(256) __half g_k16[(size_t)BATCH*HEADS*NTOK*DHEAD];
__device__ __align__(256) __half g_v16[(size_t)BATCH*HEADS*NTOK*DHEAD];
__device__ __align__(256) __half g_att16[(size_t)MTOT*CM];

// ---------------------------------------------------------------------------
// helpers
// ---------------------------------------------------------------------------
__device__ __forceinline__ uint32_t smaddr(const void* p) {
    return (uint32_t)__cvta_generic_to_shared(p);
}
__device__ __forceinline__ void ldsm4(uint32_t& r0, uint32_t& r1, uint32_t& r2,
                                      uint32_t& r3, uint32_t a) {
    asm volatile("ldmatrix.sync.aligned.m8n8.x4.shared.b16 {%0,%1,%2,%3},[%4];"
                 : "=r"(r0), "=r"(r1), "=r"(r2), "=r"(r3) : "r"(a));
}
__device__ __forceinline__ void ldsm4t(uint32_t& r0, uint32_t& r1, uint32_t& r2,
                                       uint32_t& r3, uint32_t a) {
    asm volatile("ldmatrix.sync.aligned.m8n8.x4.trans.shared.b16 {%0,%1,%2,%3},[%4];"
                 : "=r"(r0), "=r"(r1), "=r"(r2), "=r"(r3) : "r"(a));
}
__device__ __forceinline__ void mma16(float c[4], const uint32_t a[4], const uint32_t b[2]) {
    asm volatile("mma.sync.aligned.m16n8k16.row.col.f32.f16.f16.f32 "
                 "{%0,%1,%2,%3},{%4,%5,%6,%7},{%8,%9},{%0,%1,%2,%3};"
                 : "+f"(c[0]), "+f"(c[1]), "+f"(c[2]), "+f"(c[3])
                 : "r"(a[0]), "r"(a[1]), "r"(a[2]), "r"(a[3]), "r"(b[0]), "r"(b[1]));
}
__device__ __forceinline__ void cpa16(uint32_t s, const void* g) {
    asm volatile("cp.async.cg.shared.global [%0],[%1],16;" :: "r"(s), "l"(g));
}
#define CP_COMMIT() asm volatile("cp.async.commit_group;")
#define CP_WAIT(n)  asm volatile("cp.async.wait_group %0;" :: "n"(n))
__device__ __forceinline__ uint32_t h2u(float lo, float hi) {
    __half2 h = __floats2half2_rn(lo, hi);
    return *(uint32_t*)&h;
}

// ---------------------------------------------------------------------------
// fp32 -> fp16 converter, 8 elems per thread-iter
// ---------------------------------------------------------------------------
__global__ void f2h_kernel(const float4* __restrict__ src, uint4* __restrict__ dst,
                           int n8)
{
    for (int i = blockIdx.x * blockDim.x + threadIdx.x; i < n8;
         i += gridDim.x * blockDim.x) {
        float4 a = src[2 * i], b = src[2 * i + 1];
        dst[i] = make_uint4(h2u(a.x, a.y), h2u(a.z, a.w), h2u(b.x, b.y), h2u(b.z, b.w));
    }
}

// ---------------------------------------------------------------------------
// fp16 GEMM-NT: C[m,n] = sum_k A[m,k]*B[n,k] + bias[n]
// BM=BN=128, BK=32, 256 threads, warps 2x4 (tile 64x32), 4-stage cp.async.
// smem rows padded to 40 halves (80B) -> conflict-free ldmatrix/cp.async.
// MODE 0: fp32 C row-major. MODE 1: QKV scatter (q,k fp32; v fp16).
// ---------------------------------------------------------------------------
#define GST (128 * 40)          // halves per operand per stage
#define GSTAGE (2 * GST)        // A + B

template<int MODE>
__global__ __launch_bounds__(256, 2)
void gemm_h(const __half* __restrict__ A, const __half* __restrict__ B,
            const float* __restrict__ bias, float* __restrict__ C, int N, int K)
{
    extern __shared__ __half sh[];

    const int tid  = threadIdx.x;
    const int lane = tid & 31, warp = tid >> 5;
    const int g = lane >> 2, cq = lane & 3;
    const int wm = warp >> 2, wn = warp & 3;
    const int n0 = blockIdx.x * 128, m0 = blockIdx.y * 128;

    const int lrow = tid >> 2, lch = tid & 3;   // 64 rows x 4 chunks per pass
    const __half* Ag = A + (size_t)(m0 + lrow) * K + lch * 8;
    const __half* Bg = B + (size_t)(n0 + lrow) * K + lch * 8;

    float acc[4][4][4] = {};

    auto issue = [&](int s, int k0) {
        __half* As = sh + s * GSTAGE;
        __half* Bs = As + GST;
        uint32_t da = smaddr(As + lrow * 40 + lch * 8);
        uint32_t db = smaddr(Bs + lrow * 40 + lch * 8);
        cpa16(da,            Ag + k0);
        cpa16(da + 64*40*2,  Ag + (size_t)64 * K + k0);
        cpa16(db,            Bg + k0);
        cpa16(db + 64*40*2,  Bg + (size_t)64 * K + k0);
    };

    issue(0, 0);  CP_COMMIT();
    issue(1, 32); CP_COMMIT();
    issue(2, 64); CP_COMMIT();

    const int nk = K / 32;
    for (int ks = 0; ks < nk; ++ks) {
        CP_WAIT(2);
        __syncthreads();
        if (ks + 3 < nk) issue((ks + 3) & 3, (ks + 3) * 32);
        CP_COMMIT();

        const __half* As = sh + (ks & 3) * GSTAGE;
        const __half* Bs = As + GST;
        #pragma unroll
        for (int kk = 0; kk < 2; ++kk) {
            uint32_t af[4][4], bf[4][2];
            #pragma unroll
            for (int mt = 0; mt < 4; ++mt)
                ldsm4(af[mt][0], af[mt][1], af[mt][2], af[mt][3],
                      smaddr(As + (wm*64 + mt*16 + (lane & 15)) * 40
                                + kk*16 + (lane >> 4) * 8));
            #pragma unroll
            for (int p = 0; p < 2; ++p)
                ldsm4(bf[2*p][0], bf[2*p+1][0], bf[2*p][1], bf[2*p+1][1],
                      smaddr(Bs + (wn*32 + p*16 + (lane & 15)) * 40
                                + kk*16 + (lane >> 4) * 8));
            #pragma unroll
            for (int mt = 0; mt < 4; ++mt)
                #pragma unroll
                for (int nt = 0; nt < 4; ++nt)
                    mma16(acc[mt][nt], af[mt], bf[nt]);
        }
        __syncthreads();
    }

    // Epilogue: c0=[g][2cq], c1=[g][2cq+1], c2=[g+8][2cq], c3=[g+8][2cq+1]
    #pragma unroll
    for (int mt = 0; mt < 4; ++mt) {
        int r0 = m0 + wm*64 + mt*16 + g;
        int r1 = r0 + 8;
        #pragma unroll
        for (int nt = 0; nt < 4; ++nt) {
            int col = n0 + wn*32 + nt*8 + 2*cq;
            float b0 = bias[col], b1 = bias[col + 1];
            float2 v0 = make_float2(acc[mt][nt][0] + b0, acc[mt][nt][1] + b1);
            float2 v1 = make_float2(acc[mt][nt][2] + b0, acc[mt][nt][3] + b1);
            if (MODE == 0) {
                *(float2*)(C + (size_t)r0 * N + col) = v0;
                *(float2*)(C + (size_t)r1 * N + col) = v1;
            } else {
                int part = col / CM;
                int within = col % CM;
                int head = within >> 7;
                int d = within & 127;
                int b0i = r0 >> 11, t0 = r0 & (NTOK - 1);
                int b1i = r1 >> 11, t1 = r1 & (NTOK - 1);
                size_t o0 = (((size_t)b0i * HEADS + head) * NTOK + t0) * DHEAD + d;
                size_t o1 = (((size_t)b1i * HEADS + head) * NTOK + t1) * DHEAD + d;
                if (part == 0) {
                    *(float2*)(g_q + o0) = v0; *(float2*)(g_q + o1) = v1;
                } else if (part == 1) {
                    *(float2*)(g_k + o0) = v0; *(float2*)(g_k + o1) = v1;
                } else {
                    *(__half2*)(g_v16 + o0) = __floats2half2_rn(v0.x, v0.y);
                    *(__half2*)(g_v16 + o1) = __floats2half2_rn(v1.x, v1.y);
                }
            }
        }
    }
}

// ---------------------------------------------------------------------------
// RMSNorm + 3D RoPE; fp32 in (g_q/g_k), fp16 out (g_q16 pre-scaled, g_k16).
// ---------------------------------------------------------------------------
__global__ void rope_rms_kernel(const float* __restrict__ qn_w,
                                const float* __restrict__ kn_w)
{
    const int row = blockIdx.x;
    const int d   = threadIdx.x;
    const float* src = (blockIdx.y == 0) ? g_q : g_k;
    __half* dst      = (blockIdx.y == 0) ? g_q16 : g_k16;
    const float* w   = (blockIdx.y == 0) ? qn_w : kn_w;
    const float post = (blockIdx.y == 0) ? 0.08838834764831845f : 1.0f;
    const int tok = row & (NTOK - 1);

    float x = src[(size_t)row * DHEAD + d];

    __shared__ float sred[4];
    __shared__ float shv[128];
    float v = x * x;
    #pragma unroll
    for (int o = 16; o; o >>= 1) v += __shfl_xor_sync(0xffffffffu, v, o);
    if ((d & 31) == 0) sred[d >> 5] = v;
    __syncthreads();
    float ss = sred[0] + sred[1] + sred[2] + sred[3];
    float y  = x * rsqrtf(ss * (1.f / DHEAD) + 1e-6f) * w[d];
    shv[d] = y;
    __syncthreads();
    float rot = (d & 1) ? shv[d - 1] : -shv[d + 1];

    float pos, e;
    if (d < 44)      { pos = (float)(tok >> 8);        e = (float)(d & ~1)        * (1.f / 44.f); }
    else if (d < 86) { pos = (float)((tok >> 4) & 15); e = (float)((d - 44) & ~1) * (1.f / 42.f); }
    else             { pos = (float)(tok & 15);        e = (float)((d - 86) & ~1) * (1.f / 42.f); }
    float f = expf(-9.210340371976184f * e);
    float cs, sn;
    sincosf(pos * f, &sn, &cs);
    dst[(size_t)row * DHEAD + d] = __float2half_rn((y * cs + rot * sn) * post);
}

// ---------------------------------------------------------------------------
// Flash attention, fp16 mma. Block: 64 q rows, 128 threads (4 warps x 16 rows).
// Bc=64. Q frags register-resident; S-acc repacked directly as P A-frags;
// V via ldmatrix.trans from natural [kc][d] layout. 2-stage cp.async on K+V.
// smem: 2 stages x (K[64][136] + V[64][136]) halves = 69632 B.
// ---------------------------------------------------------------------------
#define FKV 8704                // 64*136 halves
#define FSTG (2 * FKV)

__global__ __launch_bounds__(128, 2)
void flash_h()
{
    extern __shared__ __half fsh[];

    const int tid = threadIdx.x, lane = tid & 31, w = tid >> 5;
    const int g = lane >> 2, cq = lane & 3;
    const int q0 = blockIdx.x * 64;
    const size_t hb = ((size_t)blockIdx.z * HEADS + blockIdx.y) * NTOK * DHEAD;
    const __half* Qg = g_q16 + hb + (size_t)q0 * DHEAD;
    const __half* Kg = g_k16 + hb;
    const __half* Vg = g_v16 + hb;

    // Stage Q into stage-0 K area, pull fragments
    {
        __half* Qs = fsh;
        #pragma unroll
        for (int it = 0; it < 8; ++it) {
            int cid = it * 128 + tid;
            int r = cid >> 4, ch = cid & 15;
            *(uint4*)(Qs + r * 136 + ch * 8) = *(const uint4*)(Qg + r * 128 + ch * 8);
        }
    }
    __syncthreads();
    uint32_t qa[8][4];
    #pragma unroll
    for (int kk = 0; kk < 8; ++kk)
        ldsm4(qa[kk][0], qa[kk][1], qa[kk][2], qa[kk][3],
              smaddr(fsh + (w*16 + (lane & 15)) * 136 + kk*16 + (lane >> 4) * 8));
    __syncthreads();

    auto issueKV = [&](int s, int c0) {
        __half* Kst = fsh + s * FSTG;
        __half* Vst = Kst + FKV;
        const __half* Kp = Kg + (size_t)c0 * DHEAD;
        const __half* Vp = Vg + (size_t)c0 * DHEAD;
        #pragma unroll
        for (int it = 0; it < 8; ++it) {
            int cid = it * 128 + tid;
            int r = cid >> 4, ch = cid & 15;
            cpa16(smaddr(Kst + r * 136 + ch * 8), Kp + r * 128 + ch * 8);
            cpa16(smaddr(Vst + r * 136 + ch * 8), Vp + r * 128 + ch * 8);
        }
    };

    float od[16][4] = {};
    float m0 = -INFINITY, m1 = -INFINITY, l0 = 0.f, l1 = 0.f;

    issueKV(0, 0); CP_COMMIT();

    for (int c = 0; c < NTOK / 64; ++c) {
        if (c + 1 < NTOK / 64) issueKV((c + 1) & 1, (c + 1) * 64);
        CP_COMMIT();
        CP_WAIT(1);
        __syncthreads();

        const __half* Kst = fsh + (c & 1) * FSTG;
        const __half* Vst = Kst + FKV;

        // S = Q.K^T
        float s[8][4] = {};
        #pragma unroll
        for (int kk = 0; kk < 8; ++kk) {
            uint32_t bf[8][2];
            #pragma unroll
            for (int p = 0; p < 4; ++p)
                ldsm4(bf[2*p][0], bf[2*p+1][0], bf[2*p][1], bf[2*p+1][1],
                      smaddr(Kst + (p*16 + (lane & 15)) * 136
                                 + kk*16 + (lane >> 4) * 8));
            #pragma unroll
            for (int nt = 0; nt < 8; ++nt)
                mma16(s[nt], qa[kk], bf[nt]);
        }

        // online softmax (row g -> s[][0,1]; row g+8 -> s[][2,3])
        float cm0 = -INFINITY, cm1 = -INFINITY;
        #pragma unroll
        for (int nt = 0; nt < 8; ++nt) {
            cm0 = fmaxf(cm0, fmaxf(s[nt][0], s[nt][1]));
            cm1 = fmaxf(cm1, fmaxf(s[nt][2], s[nt][3]));
        }
        cm0 = fmaxf(cm0, __shfl_xor_sync(0xffffffffu, cm0, 1));
        cm0 = fmaxf(cm0, __shfl_xor_sync(0xffffffffu, cm0, 2));
        cm1 = fmaxf(cm1, __shfl_xor_sync(0xffffffffu, cm1, 1));
        cm1 = fmaxf(cm1, __shfl_xor_sync(0xffffffffu, cm1, 2));
        float mn0 = fmaxf(m0, cm0), mn1 = fmaxf(m1, cm1);
        float al0 = __expf(m0 - mn0), al1 = __expf(m1 - mn1);
        m0 = mn0; m1 = mn1;

        float rs0 = 0.f, rs1 = 0.f;
        #pragma unroll
        for (int nt = 0; nt < 8; ++nt) {
            s[nt][0] = __expf(s[nt][0] - mn0); rs0 += s[nt][0];
            s[nt][1] = __expf(s[nt][1] - mn0); rs0 += s[nt][1];
            s[nt][2] = __expf(s[nt][2] - mn1); rs1 += s[nt][2];
            s[nt][3] = __expf(s[nt][3] - mn1); rs1 += s[nt][3];
        }
        rs0 += __shfl_xor_sync(0xffffffffu, rs0, 1);
        rs0 += __shfl_xor_sync(0xffffffffu, rs0, 2);
        rs1 += __shfl_xor_sync(0xffffffffu, rs1, 1);
        rs1 += __shfl_xor_sync(0xffffffffu, rs1, 2);
        l0 = l0 * al0 + rs0;
        l1 = l1 * al1 + rs1;

        #pragma unroll
        for (int dt = 0; dt < 16; ++dt) {
            od[dt][0] *= al0; od[dt][1] *= al0;
            od[dt][2] *= al1; od[dt][3] *= al1;
        }

        // P -> A fragments (direct repack of S accumulator)
        uint32_t pa[4][4];
        #pragma unroll
        for (int k2 = 0; k2 < 4; ++k2) {
            pa[k2][0] = h2u(s[2*k2][0],   s[2*k2][1]);
            pa[k2][1] = h2u(s[2*k2][2],   s[2*k2][3]);
            pa[k2][2] = h2u(s[2*k2+1][0], s[2*k2+1][1]);
            pa[k2][3] = h2u(s[2*k2+1][2], s[2*k2+1][3]);
        }

        // O += P.V  (V^T fragments via ldmatrix.trans)
        #pragma unroll
        for (int k2 = 0; k2 < 4; ++k2) {
            #pragma unroll
            for (int dp = 0; dp < 8; ++dp) {
                uint32_t v0, v1, v2, v3;
                int t = lane >> 3, r = lane & 7;
                ldsm4t(v0, v1, v2, v3,
                       smaddr(Vst + (k2*16 + (t & 1)*8 + r) * 136
                                  + dp*16 + (t >> 1)*8));
                uint32_t b0[2] = {v0, v1}, b1[2] = {v2, v3};
                mma16(od[2*dp],     pa[k2], b0);
                mma16(od[2*dp + 1], pa[k2], b1);
            }
        }
        __syncthreads();
    }

    // normalize + write fp16 att [B,N,H,D]
    float inv0 = 1.f / l0, inv1 = 1.f / l1;
    int r0 = q0 + w*16 + g, r1 = r0 + 8;
    size_t base0 = (((size_t)blockIdx.z * NTOK + r0) * HEADS + blockIdx.y) * DHEAD;
    size_t base1 = (((size_t)blockIdx.z * NTOK + r1) * HEADS + blockIdx.y) * DHEAD;
    #pragma unroll
    for (int dt = 0; dt < 16; ++dt) {
        int col = dt*8 + 2*cq;
        *(__half2*)(g_att16 + base0 + col) =
            __floats2half2_rn(od[dt][0] * inv0, od[dt][1] * inv0);
        *(__half2*)(g_att16 + base1 + col) =
            __floats2half2_rn(od[dt][2] * inv1, od[dt][3] * inv1);
    }
}

// ---------------------------------------------------------------------------
extern "C" void kernel_launch(void* const* d_in, const int* in_sizes, int n_in,
                              void* d_out, int out_size)
{
    const float* x      = (const float*)d_in[0];
    const float* qkv_w  = (const float*)d_in[1];
    const float* qkv_b  = (const float*)d_in[2];
    const float* qn_w   = (const float*)d_in[3];
    const float* kn_w   = (const float*)d_in[4];
    const float* proj_w = (const float*)d_in[5];
    const float* proj_b = (const float*)d_in[6];
    float* out = (float*)d_out;

    __half *x16, *w16, *pw16;
    cudaGetSymbolAddress((void**)&x16,  g_x16);
    cudaGetSymbolAddress((void**)&w16,  g_w16);
    cudaGetSymbolAddress((void**)&pw16, g_pw16);

    // 0) fp32 -> fp16 pre-conversion
    f2h_kernel<<<1024, 256>>>((const float4*)x,      (uint4*)x16,  MTOT * CM / 8);
    f2h_kernel<<<2048, 256>>>((const float4*)qkv_w,  (uint4*)w16,  3 * CM * CM / 8);
    f2h_kernel<<<1024, 256>>>((const float4*)proj_w, (uint4*)pw16, CM * CM / 8);

    const int gsm = 4 * GSTAGE * (int)sizeof(__half);   // 81920 B
    cudaFuncSetAttribute(gemm_h<1>, cudaFuncAttributeMaxDynamicSharedMemorySize, gsm);
    cudaFuncSetAttribute(gemm_h<0>, cudaFuncAttributeMaxDynamicSharedMemorySize, gsm);
    const int fsm = 2 * FSTG * (int)sizeof(__half);     // 69632 B
    cudaFuncSetAttribute(flash_h, cudaFuncAttributeMaxDynamicSharedMemorySize, fsm);

    // 1) QKV GEMM -> scatter (q,k fp32; v fp16)
    gemm_h<1><<<dim3(3 * CM / 128, MTOT / 128), 256, gsm>>>(
        x16, w16, qkv_b, nullptr, 3 * CM, CM);

    // 2) RMSNorm + RoPE -> fp16 q (pre-scaled), k
    rope_rms_kernel<<<dim3(BATCH * HEADS * NTOK, 2), 128>>>(qn_w, kn_w);

    // 3) Flash attention -> fp16 att [B,N,H,D]
    flash_h<<<dim3(NTOK / 64, HEADS, BATCH), 128, fsm>>>();

    // 4) Output projection -> fp32 out
    __half* att16;
    cudaGetSymbolAddress((void**)&att16, g_att16);
    gemm_h<0><<<dim3(CM / 128, MTOT / 128), 256, gsm>>>(
        att16, pw16, proj_b, out, CM, CM);
}

// round 7
// speedup vs baseline: 10.5428x; 1.5921x over previous
#include <cuda_runtime.h>
#include <cuda_fp16.h>
#include <math.h>
#include <stdint.h>

#define BATCH 2
#define NTOK  2048
#define HEADS 24
#define DHEAD 128
#define CM    3072
#define MTOT  (BATCH*NTOK)   // 4096

// fp32 scratch (q,k pre-rope)
__device__ __align__(256) float g_q[(size_t)BATCH*HEADS*NTOK*DHEAD];
__device__ __align__(256) float g_k[(size_t)BATCH*HEADS*NTOK*DHEAD];
// fp16 scratch
__device__ __align__(256) __half g_x16[(size_t)MTOT*CM];
__device__ __align__(256) __half g_w16[(size_t)3*CM*CM];
__device__ __align__(256) __half g_pw16[(size_t)CM*CM];
__device__ __align__(256) __half g_q16[(size_t)BATCH*HEADS*NTOK*DHEAD];
__device__ __align__(256) __half g_k16[(size_t)BATCH*HEADS*NTOK*DHEAD];
__device__ __align__(256) __half g_v16[(size_t)BATCH*HEADS*NTOK*DHEAD];
__device__ __align__(256) __half g_att16[(size_t)MTOT*CM];

// ---------------------------------------------------------------------------
// base-ISA helpers (legal on sm_103 and sm_103a)
// ---------------------------------------------------------------------------
__device__ __forceinline__ uint32_t smaddr(const void* p) {
    return (uint32_t)__cvta_generic_to_shared(p);
}
__device__ __forceinline__ void ldsm4(uint32_t& r0, uint32_t& r1, uint32_t& r2,
                                      uint32_t& r3, uint32_t a) {
    asm volatile("ldmatrix.sync.aligned.m8n8.x4.shared.b16 {%0,%1,%2,%3},[%4];"
                 : "=r"(r0), "=r"(r1), "=r"(r2), "=r"(r3) : "r"(a));
}
__device__ __forceinline__ void ldsm4t(uint32_t& r0, uint32_t& r1, uint32_t& r2,
                                       uint32_t& r3, uint32_t a) {
    asm volatile("ldmatrix.sync.aligned.m8n8.x4.trans.shared.b16 {%0,%1,%2,%3},[%4];"
                 : "=r"(r0), "=r"(r1), "=r"(r2), "=r"(r3) : "r"(a));
}
__device__ __forceinline__ void mma16(float c[4], const uint32_t a[4], const uint32_t b[2]) {
    asm volatile("mma.sync.aligned.m16n8k16.row.col.f32.f16.f16.f32 "
                 "{%0,%1,%2,%3},{%4,%5,%6,%7},{%8,%9},{%0,%1,%2,%3};"
                 : "+f"(c[0]), "+f"(c[1]), "+f"(c[2]), "+f"(c[3])
                 : "r"(a[0]), "r"(a[1]), "r"(a[2]), "r"(a[3]), "r"(b[0]), "r"(b[1]));
}
__device__ __forceinline__ void cpa16(uint32_t s, const void* g) {
    asm volatile("cp.async.cg.shared.global [%0],[%1],16;" :: "r"(s), "l"(g));
}
#define CP_COMMIT() asm volatile("cp.async.commit_group;")
#define CP_WAIT(n)  asm volatile("cp.async.wait_group %0;" :: "n"(n))
__device__ __forceinline__ uint32_t h2u(float lo, float hi) {
    __half2 h = __floats2half2_rn(lo, hi);
    return *(uint32_t*)&h;
}
__device__ __forceinline__ void mbar_init(uint32_t a, uint32_t c) {
    asm volatile("mbarrier.init.shared.b64 [%0], %1;" :: "r"(a), "r"(c) : "memory");
}
__device__ __forceinline__ void mbar_wait(uint32_t mbar, uint32_t parity) {
    asm volatile("{\n\t.reg .pred P1;\n\t"
                 "W_%=:\n\t"
                 "mbarrier.try_wait.parity.acquire.cta.shared::cta.b64 P1, [%0], %1, 0x989680;\n\t"
                 "@P1 bra.uni D_%=;\n\t"
                 "bra.uni W_%=;\n\t"
                 "D_%=:\n\t}" :: "r"(mbar), "r"(parity) : "memory");
}

#define SMEM_SWIZZLE_128B(o) ((o) ^ (((o) >> 3) & 0x70))

// ---------------------------------------------------------------------------
// tcgen05 helpers — only visible in the sm_103a ('a' feature) device pass.
// ---------------------------------------------------------------------------
#if defined(__CUDA_ARCH_FEAT_SM103_ALL) || defined(__CUDA_ARCH_FEAT_SM100_ALL)
#define TC_ON 1
static constexpr uint64_t SMEM_DESC_BASE_SW128 =
    (uint64_t(2)  << 61) | (uint64_t(1) << 46) | (uint64_t(64) << 32) | (uint64_t(1) << 16);
__device__ __forceinline__ uint64_t mk_desc(uint32_t a) {
    return SMEM_DESC_BASE_SW128 | ((uint64_t)(a >> 4) & 0x3FFF);
}
__device__ __forceinline__ void mma_f16_ss_cg1(uint32_t d, uint64_t ad, uint64_t bd,
                                               uint32_t idesc, bool acc) {
    uint32_t en = acc ? 1u : 0u;
    asm volatile("{\n\t.reg .pred p;\n\tsetp.ne.u32 p, %4, 0;\n\t"
                 "tcgen05.mma.cta_group::1.kind::f16 [%0], %1, %2, %3, {%5,%5,%5,%5}, p;\n\t}"
                 :: "r"(d), "l"(ad), "l"(bd), "r"(idesc), "r"(en), "r"(0u) : "memory");
}
__device__ __forceinline__ void tc_commit(uint32_t mbar) {
    asm volatile("tcgen05.commit.cta_group::1.mbarrier::arrive::one.shared::cluster.b64 [%0];"
                 :: "r"(mbar) : "memory");
}
#define LDTM_X32(r, addr) \
    asm volatile("tcgen05.ld.sync.aligned.32x32b.x32.b32 " \
        "{%0,%1,%2,%3,%4,%5,%6,%7,%8,%9,%10,%11,%12,%13,%14,%15," \
        "%16,%17,%18,%19,%20,%21,%22,%23,%24,%25,%26,%27,%28,%29,%30,%31},[%32];" \
        : "=r"((r)[0]),"=r"((r)[1]),"=r"((r)[2]),"=r"((r)[3]), \
          "=r"((r)[4]),"=r"((r)[5]),"=r"((r)[6]),"=r"((r)[7]), \
          "=r"((r)[8]),"=r"((r)[9]),"=r"((r)[10]),"=r"((r)[11]), \
          "=r"((r)[12]),"=r"((r)[13]),"=r"((r)[14]),"=r"((r)[15]), \
          "=r"((r)[16]),"=r"((r)[17]),"=r"((r)[18]),"=r"((r)[19]), \
          "=r"((r)[20]),"=r"((r)[21]),"=r"((r)[22]),"=r"((r)[23]), \
          "=r"((r)[24]),"=r"((r)[25]),"=r"((r)[26]),"=r"((r)[27]), \
          "=r"((r)[28]),"=r"((r)[29]),"=r"((r)[30]),"=r"((r)[31]) \
        : "r"(addr))
#endif

// ---------------------------------------------------------------------------
// fp32 -> fp16 converter
// ---------------------------------------------------------------------------
__global__ void f2h_kernel(const float4* __restrict__ src, uint4* __restrict__ dst,
                           int n8)
{
    for (int i = blockIdx.x * blockDim.x + threadIdx.x; i < n8;
         i += gridDim.x * blockDim.x) {
        float4 a = src[2 * i], b = src[2 * i + 1];
        dst[i] = make_uint4(h2u(a.x, a.y), h2u(a.z, a.w), h2u(b.x, b.y), h2u(b.z, b.w));
    }
}

// ---------------------------------------------------------------------------
// Unified GEMM-NT: C[m,n] = sum_k A[m,k]*B[n,k] + bias[n], K = 3072.
// Grid (N/128, M/128), 256 threads, dynamic smem 133120 B.
// sm_103a pass: tcgen05 f16 SS, BK=64, 4-stage cp.async pipeline.
//   Ledger invariant: exactly ONE cp.async commit group per mainloop iter
//   (pre-loop issues 3). At top of iter ks, 3+ks groups are committed, and
//   group index of chunk c is c, so CP_WAIT(2) retires chunk ks. Stage s is
//   refilled only after mbarrier confirms MMA batch that read s retired.
// other passes: round-4 mma.sync implementation (correct fallback).
// MODE 0: fp32 C row-major. MODE 1: QKV scatter (q,k fp32; v fp16).
// ---------------------------------------------------------------------------
#define TSTAGE  32768            // A 16KB + B 16KB per stage
#define TAB     16384
#define GEMM_SMEM 133120         // 1024 ctrl + pad + 4*32768

template<int MODE>
__global__ __launch_bounds__(256, 1)
void gemm_u(const __half* __restrict__ A, const __half* __restrict__ B,
            const float* __restrict__ bias, float* __restrict__ C, int N)
{
    extern __shared__ char ts[];
    const int tid = threadIdx.x;
    const int K = 3072, nk = 48;
    const int n0 = blockIdx.x * 128, m0 = blockIdx.y * 128;

#if defined(TC_ON)
    // ---------------- tcgen05 path ----------------
    const uint32_t sb = smaddr(ts);
    const uint32_t ab = (sb + 1024 + 1023) & ~1023u;
    const uint32_t tmem_ptr_addr = sb;
    const uint32_t mbs0 = sb + 8;

    if (tid < 32)
        asm volatile("tcgen05.alloc.cta_group::1.sync.aligned.shared::cta.b32 [%0], %1;"
                     :: "r"(tmem_ptr_addr), "r"(128u) : "memory");
    if (tid == 0)
        for (int i = 0; i < 4; ++i) mbar_init(mbs0 + 8 * i, 1);
    __syncthreads();
    uint32_t tmem;
    asm volatile("ld.shared.b32 %0,[%1];" : "=r"(tmem) : "r"(tmem_ptr_addr));

    const __half* Agb = A + (size_t)m0 * K;
    const __half* Bgb = B + (size_t)n0 * K;

    // fill stage s with k-chunk kc; issues exactly one commit group
    auto fill = [&](int s, int kc) {
        uint32_t base = ab + s * TSTAGE;
        const __half* Agp = Agb + kc * 64;
        const __half* Bgp = Bgb + kc * 64;
        #pragma unroll
        for (int it = 0; it < 4; ++it) {
            int idx = it * 256 + tid;           // 128 rows x 8 x 16B
            int r = idx >> 3, ch = idx & 7;
            cpa16(base + SMEM_SWIZZLE_128B(r * 128 + ch * 16),
                  Agp + (size_t)r * K + ch * 8);
        }
        #pragma unroll
        for (int it = 0; it < 4; ++it) {
            int idx = it * 256 + tid;
            int r = idx >> 3, ch = idx & 7;
            cpa16(base + TAB + SMEM_SWIZZLE_128B(r * 128 + ch * 16),
                  Bgp + (size_t)r * K + ch * 8);
        }
        CP_COMMIT();
    };

    fill(0, 0); fill(1, 1); fill(2, 2);        // groups 0,1,2 = chunks 0,1,2

    const uint32_t idesc = (1u << 4) | (16u << 17) | (8u << 24);  // F32,f16,N=128,M=128
    int ph[4] = {0, 0, 0, 0};

    for (int ks = 0; ks < nk; ++ks) {
        const int s = ks & 3;
        CP_WAIT(2);                 // retires groups 0..ks -> chunk ks resident
        __syncthreads();

        if (tid == 0) {
            asm volatile("fence.proxy.async.shared::cta;" ::: "memory");
            uint32_t base = ab + s * TSTAGE;
            uint64_t ad = mk_desc(base);
            uint64_t bd = mk_desc(base + TAB);
            #pragma unroll
            for (int sub = 0; sub < 4; ++sub)
                mma_f16_ss_cg1(tmem, ad + sub * 2, bd + sub * 2, idesc,
                               (ks > 0) || (sub > 0));
            tc_commit(mbs0 + 8 * s);
        }

        if (ks + 3 < nk) {
            const int nxt = (ks + 3) & 3;       // stage to refill with chunk ks+3
            if (ks >= 1) {                      // stage was used by batch ks-1
                mbar_wait(mbs0 + 8 * nxt, ph[nxt]);
                ph[nxt] ^= 1;
            }
            fill(nxt, ks + 3);                  // one commit group
        } else {
            CP_COMMIT();                        // keep one-group-per-iter ledger
        }
    }

    {   // final: wait for last MMA batch (mbar (nk-1)&3 at its tracked phase)
        const int sl = (nk - 1) & 3;
        mbar_wait(mbs0 + 8 * sl, ph[sl]);
    }
    asm volatile("tcgen05.fence::after_thread_sync;" ::: "memory");
    __syncthreads();

    // Epilogue: warps 0-3 read D (each warp its 32-lane subpartition).
    const int w = tid >> 5, lane = tid & 31;
    if (w < 4) {
        const int row = m0 + w * 32 + lane;
        #pragma unroll
        for (int chunk = 0; chunk < 4; ++chunk) {
            uint32_t dr[32];
            LDTM_X32(dr, tmem + chunk * 32);
            asm volatile("tcgen05.wait::ld.sync.aligned;" ::: "memory");
            const int col0 = n0 + chunk * 32;
            if (MODE == 0) {
                float* Crow = C + (size_t)row * N + col0;
                #pragma unroll
                for (int j = 0; j < 32; j += 4) {
                    float4 v = make_float4(__uint_as_float(dr[j])   + bias[col0 + j],
                                           __uint_as_float(dr[j+1]) + bias[col0 + j + 1],
                                           __uint_as_float(dr[j+2]) + bias[col0 + j + 2],
                                           __uint_as_float(dr[j+3]) + bias[col0 + j + 3]);
                    *(float4*)(Crow + j) = v;
                }
            } else {
                const int part = col0 / CM, within = col0 % CM;
                const int head = within >> 7, d0 = within & 127;
                const int b = row >> 11, tok = row & (NTOK - 1);
                const size_t off = (((size_t)b * HEADS + head) * NTOK + tok) * DHEAD + d0;
                if (part < 2) {
                    float* dst = ((part == 0) ? g_q : g_k) + off;
                    #pragma unroll
                    for (int j = 0; j < 32; j += 4) {
                        float4 v = make_float4(__uint_as_float(dr[j])   + bias[col0 + j],
                                               __uint_as_float(dr[j+1]) + bias[col0 + j + 1],
                                               __uint_as_float(dr[j+2]) + bias[col0 + j + 2],
                                               __uint_as_float(dr[j+3]) + bias[col0 + j + 3]);
                        *(float4*)(dst + j) = v;
                    }
                } else {
                    __half* dst = g_v16 + off;
                    #pragma unroll
                    for (int j = 0; j < 32; j += 2)
                        *(__half2*)(dst + j) = __floats2half2_rn(
                            __uint_as_float(dr[j])   + bias[col0 + j],
                            __uint_as_float(dr[j+1]) + bias[col0 + j + 1]);
                }
            }
        }
    }
    __syncthreads();
    if (tid < 32) {
        asm volatile("tcgen05.relinquish_alloc_permit.cta_group::1.sync.aligned;");
        asm volatile("tcgen05.dealloc.cta_group::1.sync.aligned.b32 %0, %1;"
                     :: "r"(tmem), "r"(128u));
    }

#else
    // ---------------- mma.sync fallback (round-4 proven) ----------------
    __half* sh = (__half*)ts;
    const int lane = tid & 31, warp = tid >> 5;
    const int g = lane >> 2, cq = lane & 3;
    const int wm = warp >> 2, wn = warp & 3;

    const int lrow = tid >> 2, lch = tid & 3;
    const __half* Ag = A + (size_t)(m0 + lrow) * K + lch * 8;
    const __half* Bg = B + (size_t)(n0 + lrow) * K + lch * 8;

    float acc[4][4][4] = {};
    const int GST = 128 * 40, GSTG = 2 * GST;

    auto issue = [&](int s, int k0) {
        __half* As = sh + s * GSTG;
        __half* Bs = As + GST;
        uint32_t da = smaddr(As + lrow * 40 + lch * 8);
        uint32_t db = smaddr(Bs + lrow * 40 + lch * 8);
        cpa16(da,            Ag + k0);
        cpa16(da + 64*40*2,  Ag + (size_t)64 * K + k0);
        cpa16(db,            Bg + k0);
        cpa16(db + 64*40*2,  Bg + (size_t)64 * K + k0);
    };

    issue(0, 0);  CP_COMMIT();
    issue(1, 32); CP_COMMIT();
    issue(2, 64); CP_COMMIT();

    const int nk32 = K / 32;
    for (int ks = 0; ks < nk32; ++ks) {
        if (ks == nk32 - 1) { CP_WAIT(0); } else { CP_WAIT(1); }
        __syncthreads();
        if (ks + 3 < nk32) issue((ks + 3) & 3, (ks + 3) * 32);
        CP_COMMIT();

        const __half* As = sh + (ks & 3) * GSTG;
        const __half* Bs = As + GST;
        #pragma unroll
        for (int kk = 0; kk < 2; ++kk) {
            uint32_t af[4][4], bf[4][2];
            #pragma unroll
            for (int mt = 0; mt < 4; ++mt)
                ldsm4(af[mt][0], af[mt][1], af[mt][2], af[mt][3],
                      smaddr(As + (wm*64 + mt*16 + (lane & 15)) * 40
                                + kk*16 + (lane >> 4) * 8));
            #pragma unroll
            for (int p = 0; p < 2; ++p)
                ldsm4(bf[2*p][0], bf[2*p+1][0], bf[2*p][1], bf[2*p+1][1],
                      smaddr(Bs + (wn*32 + p*16 + (lane & 15)) * 40
                                + kk*16 + (lane >> 4) * 8));
            #pragma unroll
            for (int mt = 0; mt < 4; ++mt)
                #pragma unroll
                for (int nt = 0; nt < 4; ++nt)
                    mma16(acc[mt][nt], af[mt], bf[nt]);
        }
        __syncthreads();
    }

    #pragma unroll
    for (int mt = 0; mt < 4; ++mt) {
        int r0 = m0 + wm*64 + mt*16 + g;
        int r1 = r0 + 8;
        #pragma unroll
        for (int nt = 0; nt < 4; ++nt) {
            int col = n0 + wn*32 + nt*8 + 2*cq;
            float b0 = bias[col], b1 = bias[col + 1];
            float2 v0 = make_float2(acc[mt][nt][0] + b0, acc[mt][nt][1] + b1);
            float2 v1 = make_float2(acc[mt][nt][2] + b0, acc[mt][nt][3] + b1);
            if (MODE == 0) {
                *(float2*)(C + (size_t)r0 * N + col) = v0;
                *(float2*)(C + (size_t)r1 * N + col) = v1;
            } else {
                int part = col / CM;
                int within = col % CM;
                int head = within >> 7;
                int d = within & 127;
                int b0i = r0 >> 11, t0 = r0 & (NTOK - 1);
                int b1i = r1 >> 11, t1 = r1 & (NTOK - 1);
                size_t o0 = (((size_t)b0i * HEADS + head) * NTOK + t0) * DHEAD + d;
                size_t o1 = (((size_t)b1i * HEADS + head) * NTOK + t1) * DHEAD + d;
                if (part == 0) {
                    *(float2*)(g_q + o0) = v0; *(float2*)(g_q + o1) = v1;
                } else if (part == 1) {
                    *(float2*)(g_k + o0) = v0; *(float2*)(g_k + o1) = v1;
                } else {
                    *(__half2*)(g_v16 + o0) = __floats2half2_rn(v0.x, v0.y);
                    *(__half2*)(g_v16 + o1) = __floats2half2_rn(v1.x, v1.y);
                }
            }
        }
    }
#endif
}

// ---------------------------------------------------------------------------
// RMSNorm + 3D RoPE; fp32 in (g_q/g_k), fp16 out (g_q16 pre-scaled, g_k16).
// ---------------------------------------------------------------------------
__global__ void rope_rms_kernel(const float* __restrict__ qn_w,
                                const float* __restrict__ kn_w)
{
    const int row = blockIdx.x;
    const int d   = threadIdx.x;
    const float* src = (blockIdx.y == 0) ? g_q : g_k;
    __half* dst      = (blockIdx.y == 0) ? g_q16 : g_k16;
    const float* w   = (blockIdx.y == 0) ? qn_w : kn_w;
    const float post = (blockIdx.y == 0) ? 0.08838834764831845f : 1.0f;
    const int tok = row & (NTOK - 1);

    float x = src[(size_t)row * DHEAD + d];

    __shared__ float sred[4];
    __shared__ float shv[128];
    float v = x * x;
    #pragma unroll
    for (int o = 16; o; o >>= 1) v += __shfl_xor_sync(0xffffffffu, v, o);
    if ((d & 31) == 0) sred[d >> 5] = v;
    __syncthreads();
    float ss = sred[0] + sred[1] + sred[2] + sred[3];
    float y  = x * rsqrtf(ss * (1.f / DHEAD) + 1e-6f) * w[d];
    shv[d] = y;
    __syncthreads();
    float rot = (d & 1) ? shv[d - 1] : -shv[d + 1];

    float pos, e;
    if (d < 44)      { pos = (float)(tok >> 8);        e = (float)(d & ~1)        * (1.f / 44.f); }
    else if (d < 86) { pos = (float)((tok >> 4) & 15); e = (float)((d - 44) & ~1) * (1.f / 42.f); }
    else             { pos = (float)(tok & 15);        e = (float)((d - 86) & ~1) * (1.f / 42.f); }
    float f = expf(-9.210340371976184f * e);
    float cs, sn;
    sincosf(pos * f, &sn, &cs);
    dst[(size_t)row * DHEAD + d] = __float2half_rn((y * cs + rot * sn) * post);
}

// ---------------------------------------------------------------------------
// Flash attention, fp16 mma.sync (round-4 proven).
// ---------------------------------------------------------------------------
#define FKV 8704                // 64*136 halves
#define FSTG (2 * FKV)

__global__ __launch_bounds__(128, 2)
void flash_h()
{
    extern __shared__ __half fsh[];

    const int tid = threadIdx.x, lane = tid & 31, w = tid >> 5;
    const int g = lane >> 2, cq = lane & 3;
    const int q0 = blockIdx.x * 64;
    const size_t hb = ((size_t)blockIdx.z * HEADS + blockIdx.y) * NTOK * DHEAD;
    const __half* Qg = g_q16 + hb + (size_t)q0 * DHEAD;
    const __half* Kg = g_k16 + hb;
    const __half* Vg = g_v16 + hb;

    {
        __half* Qs = fsh;
        #pragma unroll
        for (int it = 0; it < 8; ++it) {
            int cid = it * 128 + tid;
            int r = cid >> 4, ch = cid & 15;
            *(uint4*)(Qs + r * 136 + ch * 8) = *(const uint4*)(Qg + r * 128 + ch * 8);
        }
    }
    __syncthreads();
    uint32_t qa[8][4];
    #pragma unroll
    for (int kk = 0; kk < 8; ++kk)
        ldsm4(qa[kk][0], qa[kk][1], qa[kk][2], qa[kk][3],
              smaddr(fsh + (w*16 + (lane & 15)) * 136 + kk*16 + (lane >> 4) * 8));
    __syncthreads();

    auto issueKV = [&](int s, int c0) {
        __half* Kst = fsh + s * FSTG;
        __half* Vst = Kst + FKV;
        const __half* Kp = Kg + (size_t)c0 * DHEAD;
        const __half* Vp = Vg + (size_t)c0 * DHEAD;
        #pragma unroll
        for (int it = 0; it < 8; ++it) {
            int cid = it * 128 + tid;
            int r = cid >> 4, ch = cid & 15;
            cpa16(smaddr(Kst + r * 136 + ch * 8), Kp + r * 128 + ch * 8);
            cpa16(smaddr(Vst + r * 136 + ch * 8), Vp + r * 128 + ch * 8);
        }
    };

    float od[16][4] = {};
    float m0 = -INFINITY, m1 = -INFINITY, l0 = 0.f, l1 = 0.f;

    issueKV(0, 0); CP_COMMIT();

    for (int c = 0; c < NTOK / 64; ++c) {
        if (c + 1 < NTOK / 64) issueKV((c + 1) & 1, (c + 1) * 64);
        CP_COMMIT();
        CP_WAIT(1);
        __syncthreads();

        const __half* Kst = fsh + (c & 1) * FSTG;
        const __half* Vst = Kst + FKV;

        float s[8][4] = {};
        #pragma unroll
        for (int kk = 0; kk < 8; ++kk) {
            uint32_t bf[8][2];
            #pragma unroll
            for (int p = 0; p < 4; ++p)
                ldsm4(bf[2*p][0], bf[2*p+1][0], bf[2*p][1], bf[2*p+1][1],
                      smaddr(Kst + (p*16 + (lane & 15)) * 136
                                 + kk*16 + (lane >> 4) * 8));
            #pragma unroll
            for (int nt = 0; nt < 8; ++nt)
                mma16(s[nt], qa[kk], bf[nt]);
        }

        float cm0 = -INFINITY, cm1 = -INFINITY;
        #pragma unroll
        for (int nt = 0; nt < 8; ++nt) {
            cm0 = fmaxf(cm0, fmaxf(s[nt][0], s[nt][1]));
            cm1 = fmaxf(cm1, fmaxf(s[nt][2], s[nt][3]));
        }
        cm0 = fmaxf(cm0, __shfl_xor_sync(0xffffffffu, cm0, 1));
        cm0 = fmaxf(cm0, __shfl_xor_sync(0xffffffffu, cm0, 2));
        cm1 = fmaxf(cm1, __shfl_xor_sync(0xffffffffu, cm1, 1));
        cm1 = fmaxf(cm1, __shfl_xor_sync(0xffffffffu, cm1, 2));
        float mn0 = fmaxf(m0, cm0), mn1 = fmaxf(m1, cm1);
        float al0 = __expf(m0 - mn0), al1 = __expf(m1 - mn1);
        m0 = mn0; m1 = mn1;

        float rs0 = 0.f, rs1 = 0.f;
        #pragma unroll
        for (int nt = 0; nt < 8; ++nt) {
            s[nt][0] = __expf(s[nt][0] - mn0); rs0 += s[nt][0];
            s[nt][1] = __expf(s[nt][1] - mn0); rs0 += s[nt][1];
            s[nt][2] = __expf(s[nt][2] - mn1); rs1 += s[nt][2];
            s[nt][3] = __expf(s[nt][3] - mn1); rs1 += s[nt][3];
        }
        rs0 += __shfl_xor_sync(0xffffffffu, rs0, 1);
        rs0 += __shfl_xor_sync(0xffffffffu, rs0, 2);
        rs1 += __shfl_xor_sync(0xffffffffu, rs1, 1);
        rs1 += __shfl_xor_sync(0xffffffffu, rs1, 2);
        l0 = l0 * al0 + rs0;
        l1 = l1 * al1 + rs1;

        #pragma unroll
        for (int dt = 0; dt < 16; ++dt) {
            od[dt][0] *= al0; od[dt][1] *= al0;
            od[dt][2] *= al1; od[dt][3] *= al1;
        }

        uint32_t pa[4][4];
        #pragma unroll
        for (int k2 = 0; k2 < 4; ++k2) {
            pa[k2][0] = h2u(s[2*k2][0],   s[2*k2][1]);
            pa[k2][1] = h2u(s[2*k2][2],   s[2*k2][3]);
            pa[k2][2] = h2u(s[2*k2+1][0], s[2*k2+1][1]);
            pa[k2][3] = h2u(s[2*k2+1][2], s[2*k2+1][3]);
        }

        #pragma unroll
        for (int k2 = 0; k2 < 4; ++k2) {
            #pragma unroll
            for (int dp = 0; dp < 8; ++dp) {
                uint32_t v0, v1, v2, v3;
                int t = lane >> 3, r = lane & 7;
                ldsm4t(v0, v1, v2, v3,
                       smaddr(Vst + (k2*16 + (t & 1)*8 + r) * 136
                                  + dp*16 + (t >> 1)*8));
                uint32_t b0[2] = {v0, v1}, b1[2] = {v2, v3};
                mma16(od[2*dp],     pa[k2], b0);
                mma16(od[2*dp + 1], pa[k2], b1);
            }
        }
        __syncthreads();
    }

    float inv0 = 1.f / l0, inv1 = 1.f / l1;
    int r0 = q0 + w*16 + g, r1 = r0 + 8;
    size_t base0 = (((size_t)blockIdx.z * NTOK + r0) * HEADS + blockIdx.y) * DHEAD;
    size_t base1 = (((size_t)blockIdx.z * NTOK + r1) * HEADS + blockIdx.y) * DHEAD;
    #pragma unroll
    for (int dt = 0; dt < 16; ++dt) {
        int col = dt*8 + 2*cq;
        *(__half2*)(g_att16 + base0 + col) =
            __floats2half2_rn(od[dt][0] * inv0, od[dt][1] * inv0);
        *(__half2*)(g_att16 + base1 + col) =
            __floats2half2_rn(od[dt][2] * inv1, od[dt][3] * inv1);
    }
}

// ---------------------------------------------------------------------------
extern "C" void kernel_launch(void* const* d_in, const int* in_sizes, int n_in,
                              void* d_out, int out_size)
{
    const float* x      = (const float*)d_in[0];
    const float* qkv_w  = (const float*)d_in[1];
    const float* qkv_b  = (const float*)d_in[2];
    const float* qn_w   = (const float*)d_in[3];
    const float* kn_w   = (const float*)d_in[4];
    const float* proj_w = (const float*)d_in[5];
    const float* proj_b = (const float*)d_in[6];
    float* out = (float*)d_out;

    __half *x16, *w16, *pw16, *att16;
    cudaGetSymbolAddress((void**)&x16,   g_x16);
    cudaGetSymbolAddress((void**)&w16,   g_w16);
    cudaGetSymbolAddress((void**)&pw16,  g_pw16);
    cudaGetSymbolAddress((void**)&att16, g_att16);

    // 0) fp32 -> fp16 pre-conversion
    f2h_kernel<<<1024, 256>>>((const float4*)x,      (uint4*)x16,  MTOT * CM / 8);
    f2h_kernel<<<2048, 256>>>((const float4*)qkv_w,  (uint4*)w16,  3 * CM * CM / 8);
    f2h_kernel<<<1024, 256>>>((const float4*)proj_w, (uint4*)pw16, CM * CM / 8);

    cudaFuncSetAttribute(gemm_u<1>, cudaFuncAttributeMaxDynamicSharedMemorySize, GEMM_SMEM);
    cudaFuncSetAttribute(gemm_u<0>, cudaFuncAttributeMaxDynamicSharedMemorySize, GEMM_SMEM);
    const int fsm = 2 * FSTG * (int)sizeof(__half);     // 69632 B
    cudaFuncSetAttribute(flash_h, cudaFuncAttributeMaxDynamicSharedMemorySize, fsm);

    // 1) QKV GEMM -> scatter (q,k fp32; v fp16)
    gemm_u<1><<<dim3(3 * CM / 128, MTOT / 128), 256, GEMM_SMEM>>>(
        x16, w16, qkv_b, nullptr, 3 * CM);

    // 2) RMSNorm + RoPE -> fp16 q (pre-scaled), k
    rope_rms_kernel<<<dim3(BATCH * HEADS * NTOK, 2), 128>>>(qn_w, kn_w);

    // 3) Flash attention -> fp16 att [B,N,H,D]
    flash_h<<<dim3(NTOK / 64, HEADS, BATCH), 128, fsm>>>();

    // 4) Output projection -> fp32 out
    gemm_u<0><<<dim3(CM / 128, MTOT / 128), 256, GEMM_SMEM>>>(
        att16, pw16, proj_b, out, CM);
}

// round 8
// speedup vs baseline: 11.6534x; 1.1054x over previous
#include <cuda_runtime.h>
#include <cuda_fp16.h>
#include <math.h>
#include <stdint.h>

#define BATCH 2
#define NTOK  2048
#define HEADS 24
#define DHEAD 128
#define CM    3072
#define MTOT  (BATCH*NTOK)   // 4096

// fp32 scratch (q,k pre-rope)
__device__ __align__(256) float g_q[(size_t)BATCH*HEADS*NTOK*DHEAD];
__device__ __align__(256) float g_k[(size_t)BATCH*HEADS*NTOK*DHEAD];
// fp16 scratch
__device__ __align__(256) __half g_x16[(size_t)MTOT*CM];
__device__ __align__(256) __half g_w16[(size_t)3*CM*CM];
__device__ __align__(256) __half g_pw16[(size_t)CM*CM];
__device__ __align__(256) __half g_q16[(size_t)BATCH*HEADS*NTOK*DHEAD];
__device__ __align__(256) __half g_k16[(size_t)BATCH*HEADS*NTOK*DHEAD];
__device__ __align__(256) __half g_v16[(size_t)BATCH*HEADS*NTOK*DHEAD];
__device__ __align__(256) __half g_att16[(size_t)MTOT*CM];

// ---------------------------------------------------------------------------
// base-ISA helpers (legal on sm_103 and sm_103a)
// ---------------------------------------------------------------------------
__device__ __forceinline__ uint32_t smaddr(const void* p) {
    return (uint32_t)__cvta_generic_to_shared(p);
}
__device__ __forceinline__ void ldsm4(uint32_t& r0, uint32_t& r1, uint32_t& r2,
                                      uint32_t& r3, uint32_t a) {
    asm volatile("ldmatrix.sync.aligned.m8n8.x4.shared.b16 {%0,%1,%2,%3},[%4];"
                 : "=r"(r0), "=r"(r1), "=r"(r2), "=r"(r3) : "r"(a));
}
__device__ __forceinline__ void ldsm4t(uint32_t& r0, uint32_t& r1, uint32_t& r2,
                                       uint32_t& r3, uint32_t a) {
    asm volatile("ldmatrix.sync.aligned.m8n8.x4.trans.shared.b16 {%0,%1,%2,%3},[%4];"
                 : "=r"(r0), "=r"(r1), "=r"(r2), "=r"(r3) : "r"(a));
}
__device__ __forceinline__ void mma16(float c[4], const uint32_t a[4], const uint32_t b[2]) {
    asm volatile("mma.sync.aligned.m16n8k16.row.col.f32.f16.f16.f32 "
                 "{%0,%1,%2,%3},{%4,%5,%6,%7},{%8,%9},{%0,%1,%2,%3};"
                 : "+f"(c[0]), "+f"(c[1]), "+f"(c[2]), "+f"(c[3])
                 : "r"(a[0]), "r"(a[1]), "r"(a[2]), "r"(a[3]), "r"(b[0]), "r"(b[1]));
}
__device__ __forceinline__ void cpa16(uint32_t s, const void* g) {
    asm volatile("cp.async.cg.shared.global [%0],[%1],16;" :: "r"(s), "l"(g));
}
#define CP_COMMIT() asm volatile("cp.async.commit_group;")
#define CP_WAIT(n)  asm volatile("cp.async.wait_group %0;" :: "n"(n))
__device__ __forceinline__ uint32_t h2u(float lo, float hi) {
    __half2 h = __floats2half2_rn(lo, hi);
    return *(uint32_t*)&h;
}
__device__ __forceinline__ void mbar_init(uint32_t a, uint32_t c) {
    asm volatile("mbarrier.init.shared.b64 [%0], %1;" :: "r"(a), "r"(c) : "memory");
}
__device__ __forceinline__ void mbar_wait(uint32_t mbar, uint32_t parity) {
    asm volatile("{\n\t.reg .pred P1;\n\t"
                 "W_%=:\n\t"
                 "mbarrier.try_wait.parity.acquire.cta.shared::cta.b64 P1, [%0], %1, 0x989680;\n\t"
                 "@P1 bra.uni D_%=;\n\t"
                 "bra.uni W_%=;\n\t"
                 "D_%=:\n\t}" :: "r"(mbar), "r"(parity) : "memory");
}

#define SMEM_SWIZZLE_128B(o) ((o) ^ (((o) >> 3) & 0x70))

// ---------------------------------------------------------------------------
// tcgen05 helpers — only visible in the sm_103a ('a' feature) device pass.
// ---------------------------------------------------------------------------
#if defined(__CUDA_ARCH_FEAT_SM103_ALL) || defined(__CUDA_ARCH_FEAT_SM100_ALL)
#define TC_ON 1
static constexpr uint64_t SMEM_DESC_BASE_SW128 =
    (uint64_t(2)  << 61) | (uint64_t(1) << 46) | (uint64_t(64) << 32) | (uint64_t(1) << 16);
__device__ __forceinline__ uint64_t mk_desc(uint32_t a) {
    return SMEM_DESC_BASE_SW128 | ((uint64_t)(a >> 4) & 0x3FFF);
}
__device__ __forceinline__ void mma_f16_ss_cg1(uint32_t d, uint64_t ad, uint64_t bd,
                                               uint32_t idesc, bool acc) {
    uint32_t en = acc ? 1u : 0u;
    asm volatile("{\n\t.reg .pred p;\n\tsetp.ne.u32 p, %4, 0;\n\t"
                 "tcgen05.mma.cta_group::1.kind::f16 [%0], %1, %2, %3, {%5,%5,%5,%5}, p;\n\t}"
                 :: "r"(d), "l"(ad), "l"(bd), "r"(idesc), "r"(en), "r"(0u) : "memory");
}
__device__ __forceinline__ void tc_commit(uint32_t mbar) {
    asm volatile("tcgen05.commit.cta_group::1.mbarrier::arrive::one.shared::cluster.b64 [%0];"
                 :: "r"(mbar) : "memory");
}
#define LDTM_X32(r, addr) \
    asm volatile("tcgen05.ld.sync.aligned.32x32b.x32.b32 " \
        "{%0,%1,%2,%3,%4,%5,%6,%7,%8,%9,%10,%11,%12,%13,%14,%15," \
        "%16,%17,%18,%19,%20,%21,%22,%23,%24,%25,%26,%27,%28,%29,%30,%31},[%32];" \
        : "=r"((r)[0]),"=r"((r)[1]),"=r"((r)[2]),"=r"((r)[3]), \
          "=r"((r)[4]),"=r"((r)[5]),"=r"((r)[6]),"=r"((r)[7]), \
          "=r"((r)[8]),"=r"((r)[9]),"=r"((r)[10]),"=r"((r)[11]), \
          "=r"((r)[12]),"=r"((r)[13]),"=r"((r)[14]),"=r"((r)[15]), \
          "=r"((r)[16]),"=r"((r)[17]),"=r"((r)[18]),"=r"((r)[19]), \
          "=r"((r)[20]),"=r"((r)[21]),"=r"((r)[22]),"=r"((r)[23]), \
          "=r"((r)[24]),"=r"((r)[25]),"=r"((r)[26]),"=r"((r)[27]), \
          "=r"((r)[28]),"=r"((r)[29]),"=r"((r)[30]),"=r"((r)[31]) \
        : "r"(addr))
#endif

// ---------------------------------------------------------------------------
// fp32 -> fp16 converter
// ---------------------------------------------------------------------------
__global__ void f2h_kernel(const float4* __restrict__ src, uint4* __restrict__ dst,
                           int n8)
{
    for (int i = blockIdx.x * blockDim.x + threadIdx.x; i < n8;
         i += gridDim.x * blockDim.x) {
        float4 a = src[2 * i], b = src[2 * i + 1];
        dst[i] = make_uint4(h2u(a.x, a.y), h2u(a.z, a.w), h2u(b.x, b.y), h2u(b.z, b.w));
    }
}

// ---------------------------------------------------------------------------
// Unified GEMM-NT: C[m,n] = sum_k A[m,k]*B[n,k] + bias[n], K = 3072.
// Grid (N/256, M/128), 256 threads.
// sm_103a pass: tcgen05 f16 SS, BM=128 BN=256 BK=64, 4-stage cp.async.
//   One commit group per mainloop iter; CP_WAIT(2) retires chunk ks.
// other passes: mma.sync fallback (two 128-col halves per block).
// MODE 0: fp32 C row-major. MODE 1: QKV scatter (q,k fp32; v fp16).
// ---------------------------------------------------------------------------
#define TSTAGE  49152            // A 16KB + B 32KB per stage
#define TAB     16384
#define GEMM_SMEM (2048 + 4 * TSTAGE)   // 198656 B

template<int MODE>
__global__ __launch_bounds__(256, 1)
void gemm_u(const __half* __restrict__ A, const __half* __restrict__ B,
            const float* __restrict__ bias, float* __restrict__ C, int N)
{
    extern __shared__ char ts[];
    const int tid = threadIdx.x;
    const int K = 3072, nk = 48;
    const int n0 = blockIdx.x * 256, m0 = blockIdx.y * 128;

#if defined(TC_ON)
    // ---------------- tcgen05 path ----------------
    const uint32_t sb = smaddr(ts);
    const uint32_t ab = (sb + 1024 + 1023) & ~1023u;
    const uint32_t tmem_ptr_addr = sb;
    const uint32_t mbs0 = sb + 8;

    if (tid < 32)
        asm volatile("tcgen05.alloc.cta_group::1.sync.aligned.shared::cta.b32 [%0], %1;"
                     :: "r"(tmem_ptr_addr), "r"(256u) : "memory");
    if (tid == 0)
        for (int i = 0; i < 4; ++i) mbar_init(mbs0 + 8 * i, 1);
    __syncthreads();
    uint32_t tmem;
    asm volatile("ld.shared.b32 %0,[%1];" : "=r"(tmem) : "r"(tmem_ptr_addr));

    const __half* Agb = A + (size_t)m0 * K;
    const __half* Bgb = B + (size_t)n0 * K;

    // fill stage s with k-chunk kc; exactly one commit group
    auto fill = [&](int s, int kc) {
        uint32_t base = ab + s * TSTAGE;
        const __half* Agp = Agb + kc * 64;
        const __half* Bgp = Bgb + kc * 64;
        #pragma unroll
        for (int it = 0; it < 4; ++it) {            // A: 128 rows x 8 x 16B
            int idx = it * 256 + tid;
            int r = idx >> 3, ch = idx & 7;
            cpa16(base + SMEM_SWIZZLE_128B(r * 128 + ch * 16),
                  Agp + (size_t)r * K + ch * 8);
        }
        #pragma unroll
        for (int it = 0; it < 8; ++it) {            // B: 256 rows x 8 x 16B
            int idx = it * 256 + tid;
            int r = idx >> 3, ch = idx & 7;
            cpa16(base + TAB + SMEM_SWIZZLE_128B(r * 128 + ch * 16),
                  Bgp + (size_t)r * K + ch * 8);
        }
        CP_COMMIT();
    };

    fill(0, 0); fill(1, 1); fill(2, 2);        // groups 0,1,2 = chunks 0,1,2

    const uint32_t idesc = (1u << 4) | (32u << 17) | (8u << 24);  // F32,f16,N=256,M=128
    int ph[4] = {0, 0, 0, 0};

    for (int ks = 0; ks < nk; ++ks) {
        const int s = ks & 3;
        CP_WAIT(2);                 // chunk ks resident
        __syncthreads();

        if (tid == 0) {
            asm volatile("fence.proxy.async.shared::cta;" ::: "memory");
            uint32_t base = ab + s * TSTAGE;
            uint64_t ad = mk_desc(base);
            uint64_t bd = mk_desc(base + TAB);
            #pragma unroll
            for (int sub = 0; sub < 4; ++sub)
                mma_f16_ss_cg1(tmem, ad + sub * 2, bd + sub * 2, idesc,
                               (ks > 0) || (sub > 0));
            tc_commit(mbs0 + 8 * s);
        }

        if (ks + 3 < nk) {
            const int nxt = (ks + 3) & 3;
            if (ks >= 1) {
                mbar_wait(mbs0 + 8 * nxt, ph[nxt]);
                ph[nxt] ^= 1;
            }
            fill(nxt, ks + 3);
        } else {
            CP_COMMIT();            // keep one-group-per-iter ledger
        }
    }

    {   // final: wait for last MMA batch
        const int sl = (nk - 1) & 3;
        mbar_wait(mbs0 + 8 * sl, ph[sl]);
    }
    asm volatile("tcgen05.fence::after_thread_sync;" ::: "memory");
    __syncthreads();

    // Epilogue: warps 0-3 read D (128 lanes x 256 cols), 8 chunks of 32 cols.
    const int w = tid >> 5, lane = tid & 31;
    if (w < 4) {
        const int row = m0 + w * 32 + lane;
        #pragma unroll
        for (int chunk = 0; chunk < 8; ++chunk) {
            uint32_t dr[32];
            LDTM_X32(dr, tmem + chunk * 32);
            asm volatile("tcgen05.wait::ld.sync.aligned;" ::: "memory");
            const int col0 = n0 + chunk * 32;
            if (MODE == 0) {
                float* Crow = C + (size_t)row * N + col0;
                #pragma unroll
                for (int j = 0; j < 32; j += 4) {
                    float4 v = make_float4(__uint_as_float(dr[j])   + bias[col0 + j],
                                           __uint_as_float(dr[j+1]) + bias[col0 + j + 1],
                                           __uint_as_float(dr[j+2]) + bias[col0 + j + 2],
                                           __uint_as_float(dr[j+3]) + bias[col0 + j + 3]);
                    *(float4*)(Crow + j) = v;
                }
            } else {
                const int part = col0 / CM, within = col0 % CM;
                const int head = within >> 7, d0 = within & 127;
                const int b = row >> 11, tok = row & (NTOK - 1);
                const size_t off = (((size_t)b * HEADS + head) * NTOK + tok) * DHEAD + d0;
                if (part < 2) {
                    float* dst = ((part == 0) ? g_q : g_k) + off;
                    #pragma unroll
                    for (int j = 0; j < 32; j += 4) {
                        float4 v = make_float4(__uint_as_float(dr[j])   + bias[col0 + j],
                                               __uint_as_float(dr[j+1]) + bias[col0 + j + 1],
                                               __uint_as_float(dr[j+2]) + bias[col0 + j + 2],
                                               __uint_as_float(dr[j+3]) + bias[col0 + j + 3]);
                        *(float4*)(dst + j) = v;
                    }
                } else {
                    __half* dst = g_v16 + off;
                    #pragma unroll
                    for (int j = 0; j < 32; j += 2)
                        *(__half2*)(dst + j) = __floats2half2_rn(
                            __uint_as_float(dr[j])   + bias[col0 + j],
                            __uint_as_float(dr[j+1]) + bias[col0 + j + 1]);
                }
            }
        }
    }
    __syncthreads();
    if (tid < 32) {
        asm volatile("tcgen05.relinquish_alloc_permit.cta_group::1.sync.aligned;");
        asm volatile("tcgen05.dealloc.cta_group::1.sync.aligned.b32 %0, %1;"
                     :: "r"(tmem), "r"(256u));
    }

#else
    // ---------------- mma.sync fallback: two 128-col halves ----------------
    __half* sh = (__half*)ts;
    const int lane = tid & 31, warp = tid >> 5;
    const int g = lane >> 2, cq = lane & 3;
    const int wm = warp >> 2, wn = warp & 3;
    const int GST = 128 * 40, GSTG = 2 * GST;

    for (int half = 0; half < 2; ++half) {
        const int nh0 = n0 + half * 128;
        const int lrow = tid >> 2, lch = tid & 3;
        const __half* Ag = A + (size_t)(m0 + lrow) * K + lch * 8;
        const __half* Bg = B + (size_t)(nh0 + lrow) * K + lch * 8;

        float acc[4][4][4] = {};

        auto issue = [&](int s, int k0) {
            __half* As = sh + s * GSTG;
            __half* Bs = As + GST;
            uint32_t da = smaddr(As + lrow * 40 + lch * 8);
            uint32_t db = smaddr(Bs + lrow * 40 + lch * 8);
            cpa16(da,            Ag + k0);
            cpa16(da + 64*40*2,  Ag + (size_t)64 * K + k0);
            cpa16(db,            Bg + k0);
            cpa16(db + 64*40*2,  Bg + (size_t)64 * K + k0);
        };

        issue(0, 0);  CP_COMMIT();
        issue(1, 32); CP_COMMIT();
        issue(2, 64); CP_COMMIT();

        const int nk32 = K / 32;
        for (int ks = 0; ks < nk32; ++ks) {
            if (ks == nk32 - 1) { CP_WAIT(0); } else { CP_WAIT(1); }
            __syncthreads();
            if (ks + 3 < nk32) issue((ks + 3) & 3, (ks + 3) * 32);
            CP_COMMIT();

            const __half* As = sh + (ks & 3) * GSTG;
            const __half* Bs = As + GST;
            #pragma unroll
            for (int kk = 0; kk < 2; ++kk) {
                uint32_t af[4][4], bf[4][2];
                #pragma unroll
                for (int mt = 0; mt < 4; ++mt)
                    ldsm4(af[mt][0], af[mt][1], af[mt][2], af[mt][3],
                          smaddr(As + (wm*64 + mt*16 + (lane & 15)) * 40
                                    + kk*16 + (lane >> 4) * 8));
                #pragma unroll
                for (int p = 0; p < 2; ++p)
                    ldsm4(bf[2*p][0], bf[2*p+1][0], bf[2*p][1], bf[2*p+1][1],
                          smaddr(Bs + (wn*32 + p*16 + (lane & 15)) * 40
                                    + kk*16 + (lane >> 4) * 8));
                #pragma unroll
                for (int mt = 0; mt < 4; ++mt)
                    #pragma unroll
                    for (int nt = 0; nt < 4; ++nt)
                        mma16(acc[mt][nt], af[mt], bf[nt]);
            }
            __syncthreads();
        }

        #pragma unroll
        for (int mt = 0; mt < 4; ++mt) {
            int r0 = m0 + wm*64 + mt*16 + g;
            int r1 = r0 + 8;
            #pragma unroll
            for (int nt = 0; nt < 4; ++nt) {
                int col = nh0 + wn*32 + nt*8 + 2*cq;
                float b0 = bias[col], b1 = bias[col + 1];
                float2 v0 = make_float2(acc[mt][nt][0] + b0, acc[mt][nt][1] + b1);
                float2 v1 = make_float2(acc[mt][nt][2] + b0, acc[mt][nt][3] + b1);
                if (MODE == 0) {
                    *(float2*)(C + (size_t)r0 * N + col) = v0;
                    *(float2*)(C + (size_t)r1 * N + col) = v1;
                } else {
                    int part = col / CM;
                    int within = col % CM;
                    int head = within >> 7;
                    int d = within & 127;
                    int b0i = r0 >> 11, t0 = r0 & (NTOK - 1);
                    int b1i = r1 >> 11, t1 = r1 & (NTOK - 1);
                    size_t o0 = (((size_t)b0i * HEADS + head) * NTOK + t0) * DHEAD + d;
                    size_t o1 = (((size_t)b1i * HEADS + head) * NTOK + t1) * DHEAD + d;
                    if (part == 0) {
                        *(float2*)(g_q + o0) = v0; *(float2*)(g_q + o1) = v1;
                    } else if (part == 1) {
                        *(float2*)(g_k + o0) = v0; *(float2*)(g_k + o1) = v1;
                    } else {
                        *(__half2*)(g_v16 + o0) = __floats2half2_rn(v0.x, v0.y);
                        *(__half2*)(g_v16 + o1) = __floats2half2_rn(v1.x, v1.y);
                    }
                }
            }
        }
        __syncthreads();
    }
#endif
}

// ---------------------------------------------------------------------------
// RMSNorm + 3D RoPE; fp32 in (g_q/g_k), fp16 out (g_q16 pre-scaled, g_k16).
// ---------------------------------------------------------------------------
__global__ void rope_rms_kernel(const float* __restrict__ qn_w,
                                const float* __restrict__ kn_w)
{
    const int row = blockIdx.x;
    const int d   = threadIdx.x;
    const float* src = (blockIdx.y == 0) ? g_q : g_k;
    __half* dst      = (blockIdx.y == 0) ? g_q16 : g_k16;
    const float* w   = (blockIdx.y == 0) ? qn_w : kn_w;
    const float post = (blockIdx.y == 0) ? 0.08838834764831845f : 1.0f;
    const int tok = row & (NTOK - 1);

    float x = src[(size_t)row * DHEAD + d];

    __shared__ float sred[4];
    __shared__ float shv[128];
    float v = x * x;
    #pragma unroll
    for (int o = 16; o; o >>= 1) v += __shfl_xor_sync(0xffffffffu, v, o);
    if ((d & 31) == 0) sred[d >> 5] = v;
    __syncthreads();
    float ss = sred[0] + sred[1] + sred[2] + sred[3];
    float y  = x * rsqrtf(ss * (1.f / DHEAD) + 1e-6f) * w[d];
    shv[d] = y;
    __syncthreads();
    float rot = (d & 1) ? shv[d - 1] : -shv[d + 1];

    float pos, e;
    if (d < 44)      { pos = (float)(tok >> 8);        e = (float)(d & ~1)        * (1.f / 44.f); }
    else if (d < 86) { pos = (float)((tok >> 4) & 15); e = (float)((d - 44) & ~1) * (1.f / 42.f); }
    else             { pos = (float)(tok & 15);        e = (float)((d - 86) & ~1) * (1.f / 42.f); }
    float f = expf(-9.210340371976184f * e);
    float cs, sn;
    sincosf(pos * f, &sn, &cs);
    dst[(size_t)row * DHEAD + d] = __float2half_rn((y * cs + rot * sn) * post);
}

// ---------------------------------------------------------------------------
// Flash attention, fp16 mma.sync. Br=128 (8 warps x 16 rows), Bc=64.
// Per-warp math identical to the round-4 proven version.
// smem: 2 stages x (K[64][136] + V[64][136]) halves = 69632 B.
// ---------------------------------------------------------------------------
#define FKV 8704                // 64*136 halves
#define FSTG (2 * FKV)

__global__ __launch_bounds__(256, 2)
void flash_h()
{
    extern __shared__ __half fsh[];

    const int tid = threadIdx.x, lane = tid & 31, w = tid >> 5;
    const int g = lane >> 2, cq = lane & 3;
    const int q0 = blockIdx.x * 128;
    const size_t hb = ((size_t)blockIdx.z * HEADS + blockIdx.y) * NTOK * DHEAD;
    const __half* Qg = g_q16 + hb + (size_t)q0 * DHEAD;
    const __half* Kg = g_k16 + hb;
    const __half* Vg = g_v16 + hb;

    {   // stage Q (128 rows x 128 cols) across the stage-0 K+V area
        #pragma unroll
        for (int it = 0; it < 8; ++it) {
            int cid = it * 256 + tid;
            int r = cid >> 4, ch = cid & 15;
            *(uint4*)(fsh + r * 136 + ch * 8) = *(const uint4*)(Qg + r * 128 + ch * 8);
        }
    }
    __syncthreads();
    uint32_t qa[8][4];
    #pragma unroll
    for (int kk = 0; kk < 8; ++kk)
        ldsm4(qa[kk][0], qa[kk][1], qa[kk][2], qa[kk][3],
              smaddr(fsh + (w*16 + (lane & 15)) * 136 + kk*16 + (lane >> 4) * 8));
    __syncthreads();

    auto issueKV = [&](int s, int c0) {
        __half* Kst = fsh + s * FSTG;
        __half* Vst = Kst + FKV;
        const __half* Kp = Kg + (size_t)c0 * DHEAD;
        const __half* Vp = Vg + (size_t)c0 * DHEAD;
        #pragma unroll
        for (int it = 0; it < 4; ++it) {
            int cid = it * 256 + tid;
            int r = cid >> 4, ch = cid & 15;
            cpa16(smaddr(Kst + r * 136 + ch * 8), Kp + r * 128 + ch * 8);
            cpa16(smaddr(Vst + r * 136 + ch * 8), Vp + r * 128 + ch * 8);
        }
    };

    float od[16][4] = {};
    float m0 = -INFINITY, m1 = -INFINITY, l0 = 0.f, l1 = 0.f;

    issueKV(0, 0); CP_COMMIT();

    for (int c = 0; c < NTOK / 64; ++c) {
        if (c + 1 < NTOK / 64) issueKV((c + 1) & 1, (c + 1) * 64);
        CP_COMMIT();
        CP_WAIT(1);
        __syncthreads();

        const __half* Kst = fsh + (c & 1) * FSTG;
        const __half* Vst = Kst + FKV;

        float s[8][4] = {};
        #pragma unroll
        for (int kk = 0; kk < 8; ++kk) {
            uint32_t bf[8][2];
            #pragma unroll
            for (int p = 0; p < 4; ++p)
                ldsm4(bf[2*p][0], bf[2*p+1][0], bf[2*p][1], bf[2*p+1][1],
                      smaddr(Kst + (p*16 + (lane & 15)) * 136
                                 + kk*16 + (lane >> 4) * 8));
            #pragma unroll
            for (int nt = 0; nt < 8; ++nt)
                mma16(s[nt], qa[kk], bf[nt]);
        }

        float cm0 = -INFINITY, cm1 = -INFINITY;
        #pragma unroll
        for (int nt = 0; nt < 8; ++nt) {
            cm0 = fmaxf(cm0, fmaxf(s[nt][0], s[nt][1]));
            cm1 = fmaxf(cm1, fmaxf(s[nt][2], s[nt][3]));
        }
        cm0 = fmaxf(cm0, __shfl_xor_sync(0xffffffffu, cm0, 1));
        cm0 = fmaxf(cm0, __shfl_xor_sync(0xffffffffu, cm0, 2));
        cm1 = fmaxf(cm1, __shfl_xor_sync(0xffffffffu, cm1, 1));
        cm1 = fmaxf(cm1, __shfl_xor_sync(0xffffffffu, cm1, 2));
        float mn0 = fmaxf(m0, cm0), mn1 = fmaxf(m1, cm1);
        float al0 = __expf(m0 - mn0), al1 = __expf(m1 - mn1);
        m0 = mn0; m1 = mn1;

        float rs0 = 0.f, rs1 = 0.f;
        #pragma unroll
        for (int nt = 0; nt < 8; ++nt) {
            s[nt][0] = __expf(s[nt][0] - mn0); rs0 += s[nt][0];
            s[nt][1] = __expf(s[nt][1] - mn0); rs0 += s[nt][1];
            s[nt][2] = __expf(s[nt][2] - mn1); rs1 += s[nt][2];
            s[nt][3] = __expf(s[nt][3] - mn1); rs1 += s[nt][3];
        }
        rs0 += __shfl_xor_sync(0xffffffffu, rs0, 1);
        rs0 += __shfl_xor_sync(0xffffffffu, rs0, 2);
        rs1 += __shfl_xor_sync(0xffffffffu, rs1, 1);
        rs1 += __shfl_xor_sync(0xffffffffu, rs1, 2);
        l0 = l0 * al0 + rs0;
        l1 = l1 * al1 + rs1;

        #pragma unroll
        for (int dt = 0; dt < 16; ++dt) {
            od[dt][0] *= al0; od[dt][1] *= al0;
            od[dt][2] *= al1; od[dt][3] *= al1;
        }

        uint32_t pa[4][4];
        #pragma unroll
        for (int k2 = 0; k2 < 4; ++k2) {
            pa[k2][0] = h2u(s[2*k2][0],   s[2*k2][1]);
            pa[k2][1] = h2u(s[2*k2][2],   s[2*k2][3]);
            pa[k2][2] = h2u(s[2*k2+1][0], s[2*k2+1][1]);
            pa[k2][3] = h2u(s[2*k2+1][2], s[2*k2+1][3]);
        }

        #pragma unroll
        for (int k2 = 0; k2 < 4; ++k2) {
            #pragma unroll
            for (int dp = 0; dp < 8; ++dp) {
                uint32_t v0, v1, v2, v3;
                int t = lane >> 3, r = lane & 7;
                ldsm4t(v0, v1, v2, v3,
                       smaddr(Vst + (k2*16 + (t & 1)*8 + r) * 136
                                  + dp*16 + (t >> 1)*8));
                uint32_t b0[2] = {v0, v1}, b1[2] = {v2, v3};
                mma16(od[2*dp],     pa[k2], b0);
                mma16(od[2*dp + 1], pa[k2], b1);
            }
        }
        __syncthreads();
    }

    float inv0 = 1.f / l0, inv1 = 1.f / l1;
    int r0 = q0 + w*16 + g, r1 = r0 + 8;
    size_t base0 = (((size_t)blockIdx.z * NTOK + r0) * HEADS + blockIdx.y) * DHEAD;
    size_t base1 = (((size_t)blockIdx.z * NTOK + r1) * HEADS + blockIdx.y) * DHEAD;
    #pragma unroll
    for (int dt = 0; dt < 16; ++dt) {
        int col = dt*8 + 2*cq;
        *(__half2*)(g_att16 + base0 + col) =
            __floats2half2_rn(od[dt][0] * inv0, od[dt][1] * inv0);
        *(__half2*)(g_att16 + base1 + col) =
            __floats2half2_rn(od[dt][2] * inv1, od[dt][3] * inv1);
    }
}

// ---------------------------------------------------------------------------
extern "C" void kernel_launch(void* const* d_in, const int* in_sizes, int n_in,
                              void* d_out, int out_size)
{
    const float* x      = (const float*)d_in[0];
    const float* qkv_w  = (const float*)d_in[1];
    const float* qkv_b  = (const float*)d_in[2];
    const float* qn_w   = (const float*)d_in[3];
    const float* kn_w   = (const float*)d_in[4];
    const float* proj_w = (const float*)d_in[5];
    const float* proj_b = (const float*)d_in[6];
    float* out = (float*)d_out;

    __half *x16, *w16, *pw16, *att16;
    cudaGetSymbolAddress((void**)&x16,   g_x16);
    cudaGetSymbolAddress((void**)&w16,   g_w16);
    cudaGetSymbolAddress((void**)&pw16,  g_pw16);
    cudaGetSymbolAddress((void**)&att16, g_att16);

    // 0) fp32 -> fp16 pre-conversion
    f2h_kernel<<<1024, 256>>>((const float4*)x,      (uint4*)x16,  MTOT * CM / 8);
    f2h_kernel<<<2048, 256>>>((const float4*)qkv_w,  (uint4*)w16,  3 * CM * CM / 8);
    f2h_kernel<<<1024, 256>>>((const float4*)proj_w, (uint4*)pw16, CM * CM / 8);

    cudaFuncSetAttribute(gemm_u<1>, cudaFuncAttributeMaxDynamicSharedMemorySize, GEMM_SMEM);
    cudaFuncSetAttribute(gemm_u<0>, cudaFuncAttributeMaxDynamicSharedMemorySize, GEMM_SMEM);
    const int fsm = 2 * FSTG * (int)sizeof(__half);     // 69632 B
    cudaFuncSetAttribute(flash_h, cudaFuncAttributeMaxDynamicSharedMemorySize, fsm);

    // 1) QKV GEMM -> scatter (q,k fp32; v fp16)
    gemm_u<1><<<dim3(3 * CM / 256, MTOT / 128), 256, GEMM_SMEM>>>(
        x16, w16, qkv_b, nullptr, 3 * CM);

    // 2) RMSNorm + RoPE -> fp16 q (pre-scaled), k
    rope_rms_kernel<<<dim3(BATCH * HEADS * NTOK, 2), 128>>>(qn_w, kn_w);

    // 3) Flash attention -> fp16 att [B,N,H,D]
    flash_h<<<dim3(NTOK / 128, HEADS, BATCH), 256, fsm>>>();

    // 4) Output projection -> fp32 out
    gemm_u<0><<<dim3(CM / 256, MTOT / 128), 256, GEMM_SMEM>>>(
        att16, pw16, proj_b, out, CM);
}

// round 9
// speedup vs baseline: 13.4935x; 1.1579x over previous
#include <cuda_runtime.h>
#include <cuda_fp16.h>
#include <math.h>
#include <stdint.h>

#define BATCH 2
#define NTOK  2048
#define HEADS 24
#define DHEAD 128
#define CM    3072
#define MTOT  (BATCH*NTOK)   // 4096

// fp32 scratch (q,k pre-rope) — used only by the non-'a' fallback path.
__device__ __align__(256) float g_q[(size_t)BATCH*HEADS*NTOK*DHEAD];
__device__ __align__(256) float g_k[(size_t)BATCH*HEADS*NTOK*DHEAD];
// fp16 scratch
__device__ __align__(256) __half g_x16[(size_t)MTOT*CM];
__device__ __align__(256) __half g_w16[(size_t)3*CM*CM];
__device__ __align__(256) __half g_pw16[(size_t)CM*CM];
__device__ __align__(256) __half g_q16[(size_t)BATCH*HEADS*NTOK*DHEAD];
__device__ __align__(256) __half g_k16[(size_t)BATCH*HEADS*NTOK*DHEAD];
__device__ __align__(256) __half g_v16[(size_t)BATCH*HEADS*NTOK*DHEAD];
__device__ __align__(256) __half g_att16[(size_t)MTOT*CM];
// RoPE cos/sin table: [tok][pair] (pair p covers dims 2p,2p+1)
__device__ __align__(256) float2 g_rtab[(size_t)NTOK*64];

// ---------------------------------------------------------------------------
// base-ISA helpers (legal on sm_103 and sm_103a)
// ---------------------------------------------------------------------------
__device__ __forceinline__ uint32_t smaddr(const void* p) {
    return (uint32_t)__cvta_generic_to_shared(p);
}
__device__ __forceinline__ void ldsm4(uint32_t& r0, uint32_t& r1, uint32_t& r2,
                                      uint32_t& r3, uint32_t a) {
    asm volatile("ldmatrix.sync.aligned.m8n8.x4.shared.b16 {%0,%1,%2,%3},[%4];"
                 : "=r"(r0), "=r"(r1), "=r"(r2), "=r"(r3) : "r"(a));
}
__device__ __forceinline__ void ldsm4t(uint32_t& r0, uint32_t& r1, uint32_t& r2,
                                       uint32_t& r3, uint32_t a) {
    asm volatile("ldmatrix.sync.aligned.m8n8.x4.trans.shared.b16 {%0,%1,%2,%3},[%4];"
                 : "=r"(r0), "=r"(r1), "=r"(r2), "=r"(r3) : "r"(a));
}
__device__ __forceinline__ void mma16(float c[4], const uint32_t a[4], const uint32_t b[2]) {
    asm volatile("mma.sync.aligned.m16n8k16.row.col.f32.f16.f16.f32 "
                 "{%0,%1,%2,%3},{%4,%5,%6,%7},{%8,%9},{%0,%1,%2,%3};"
                 : "+f"(c[0]), "+f"(c[1]), "+f"(c[2]), "+f"(c[3])
                 : "r"(a[0]), "r"(a[1]), "r"(a[2]), "r"(a[3]), "r"(b[0]), "r"(b[1]));
}
__device__ __forceinline__ void cpa16(uint32_t s, const void* g) {
    asm volatile("cp.async.cg.shared.global [%0],[%1],16;" :: "r"(s), "l"(g));
}
#define CP_COMMIT() asm volatile("cp.async.commit_group;")
#define CP_WAIT(n)  asm volatile("cp.async.wait_group %0;" :: "n"(n))
__device__ __forceinline__ uint32_t h2u(float lo, float hi) {
    __half2 h = __floats2half2_rn(lo, hi);
    return *(uint32_t*)&h;
}
__device__ __forceinline__ void mbar_init(uint32_t a, uint32_t c) {
    asm volatile("mbarrier.init.shared.b64 [%0], %1;" :: "r"(a), "r"(c) : "memory");
}
__device__ __forceinline__ void mbar_wait(uint32_t mbar, uint32_t parity) {
    asm volatile("{\n\t.reg .pred P1;\n\t"
                 "W_%=:\n\t"
                 "mbarrier.try_wait.parity.acquire.cta.shared::cta.b64 P1, [%0], %1, 0x989680;\n\t"
                 "@P1 bra.uni D_%=;\n\t"
                 "bra.uni W_%=;\n\t"
                 "D_%=:\n\t}" :: "r"(mbar), "r"(parity) : "memory");
}

#define SMEM_SWIZZLE_128B(o) ((o) ^ (((o) >> 3) & 0x70))

// ---------------------------------------------------------------------------
// tcgen05 helpers — only visible in the sm_103a ('a' feature) device pass.
// ---------------------------------------------------------------------------
#if defined(__CUDA_ARCH_FEAT_SM103_ALL) || defined(__CUDA_ARCH_FEAT_SM100_ALL)
#define TC_ON 1
static constexpr uint64_t SMEM_DESC_BASE_SW128 =
    (uint64_t(2)  << 61) | (uint64_t(1) << 46) | (uint64_t(64) << 32) | (uint64_t(1) << 16);
__device__ __forceinline__ uint64_t mk_desc(uint32_t a) {
    return SMEM_DESC_BASE_SW128 | ((uint64_t)(a >> 4) & 0x3FFF);
}
__device__ __forceinline__ void mma_f16_ss_cg1(uint32_t d, uint64_t ad, uint64_t bd,
                                               uint32_t idesc, bool acc) {
    uint32_t en = acc ? 1u : 0u;
    asm volatile("{\n\t.reg .pred p;\n\tsetp.ne.u32 p, %4, 0;\n\t"
                 "tcgen05.mma.cta_group::1.kind::f16 [%0], %1, %2, %3, {%5,%5,%5,%5}, p;\n\t}"
                 :: "r"(d), "l"(ad), "l"(bd), "r"(idesc), "r"(en), "r"(0u) : "memory");
}
__device__ __forceinline__ void tc_commit(uint32_t mbar) {
    asm volatile("tcgen05.commit.cta_group::1.mbarrier::arrive::one.shared::cluster.b64 [%0];"
                 :: "r"(mbar) : "memory");
}
#define LDTM_X32(r, addr) \
    asm volatile("tcgen05.ld.sync.aligned.32x32b.x32.b32 " \
        "{%0,%1,%2,%3,%4,%5,%6,%7,%8,%9,%10,%11,%12,%13,%14,%15," \
        "%16,%17,%18,%19,%20,%21,%22,%23,%24,%25,%26,%27,%28,%29,%30,%31},[%32];" \
        : "=r"((r)[0]),"=r"((r)[1]),"=r"((r)[2]),"=r"((r)[3]), \
          "=r"((r)[4]),"=r"((r)[5]),"=r"((r)[6]),"=r"((r)[7]), \
          "=r"((r)[8]),"=r"((r)[9]),"=r"((r)[10]),"=r"((r)[11]), \
          "=r"((r)[12]),"=r"((r)[13]),"=r"((r)[14]),"=r"((r)[15]), \
          "=r"((r)[16]),"=r"((r)[17]),"=r"((r)[18]),"=r"((r)[19]), \
          "=r"((r)[20]),"=r"((r)[21]),"=r"((r)[22]),"=r"((r)[23]), \
          "=r"((r)[24]),"=r"((r)[25]),"=r"((r)[26]),"=r"((r)[27]), \
          "=r"((r)[28]),"=r"((r)[29]),"=r"((r)[30]),"=r"((r)[31]) \
        : "r"(addr))
#endif

// ---------------------------------------------------------------------------
// fp32 -> fp16 converter
// ---------------------------------------------------------------------------
__global__ void f2h_kernel(const float4* __restrict__ src, uint4* __restrict__ dst,
                           int n8)
{
    for (int i = blockIdx.x * blockDim.x + threadIdx.x; i < n8;
         i += gridDim.x * blockDim.x) {
        float4 a = src[2 * i], b = src[2 * i + 1];
        dst[i] = make_uint4(h2u(a.x, a.y), h2u(a.z, a.w), h2u(b.x, b.y), h2u(b.z, b.w));
    }
}

// ---------------------------------------------------------------------------
// RoPE table: per (tok, pair) cos/sin. Pairs stay within one freq region.
// ---------------------------------------------------------------------------
__global__ void rope_tab_kernel()
{
    int idx = blockIdx.x * 64 + threadIdx.x;
    int tok = idx >> 6, p = idx & 63;
    int d = 2 * p;
    float pos, e;
    if (d < 44)      { pos = (float)(tok >> 8);        e = (float)d        * (1.f / 44.f); }
    else if (d < 86) { pos = (float)((tok >> 4) & 15); e = (float)(d - 44) * (1.f / 42.f); }
    else             { pos = (float)(tok & 15);        e = (float)(d - 86) * (1.f / 42.f); }
    float f = expf(-9.210340371976184f * e);
    float cs, sn;
    sincosf(pos * f, &sn, &cs);
    g_rtab[idx] = make_float2(cs, sn);
}

// ---------------------------------------------------------------------------
// Unified GEMM-NT: C[m,n] = sum_k A[m,k]*B[n,k] + bias[n], K = 3072.
// Grid (N/256, M/128), 256 threads.
// sm_103a: tcgen05 f16 SS, BM=128 BN=256 BK=64, 4-stage cp.async
//   (one commit group per iter; CP_WAIT(2) retires chunk ks).
// MODE 0: fp32 C row-major.
// MODE 1: QKV epilogue: q,k get fused bias+RMSNorm+RoPE -> fp16 (q pre-scaled);
//         v gets bias -> fp16. (Fallback path lacks the rope fusion; it never
//         executes on sm_103a — 'a' SASS is always loaded there.)
// ---------------------------------------------------------------------------
#define TSTAGE  49152            // A 16KB + B 32KB per stage
#define TAB     16384
#define GEMM_SMEM (3072 + 4 * TSTAGE)

template<int MODE>
__global__ __launch_bounds__(256, 1)
void gemm_u(const __half* __restrict__ A, const __half* __restrict__ B,
            const float* __restrict__ bias, float* __restrict__ C, int N,
            const float* __restrict__ qn_w, const float* __restrict__ kn_w)
{
    extern __shared__ char ts[];
    const int tid = threadIdx.x;
    const int K = 3072, nk = 48;
    const int n0 = blockIdx.x * 256, m0 = blockIdx.y * 128;

#if defined(TC_ON)
    // ---------------- tcgen05 path ----------------
    const uint32_t sb = smaddr(ts);
    const uint32_t ab = (sb + 2048 + 1023) & ~1023u;
    const uint32_t tmem_ptr_addr = sb;
    const uint32_t mbs0 = sb + 8;
    float* wsm = (float*)ts + 64;      // byte offset 256: [0:128)=qn, [128:256)=kn

    if (tid < 32)
        asm volatile("tcgen05.alloc.cta_group::1.sync.aligned.shared::cta.b32 [%0], %1;"
                     :: "r"(tmem_ptr_addr), "r"(256u) : "memory");
    if (tid == 0)
        for (int i = 0; i < 4; ++i) mbar_init(mbs0 + 8 * i, 1);
    if (MODE == 1) {
        if (tid < 128) wsm[tid] = qn_w[tid];
        else           wsm[tid] = kn_w[tid - 128];
    }
    __syncthreads();
    uint32_t tmem;
    asm volatile("ld.shared.b32 %0,[%1];" : "=r"(tmem) : "r"(tmem_ptr_addr));

    const __half* Agb = A + (size_t)m0 * K;
    const __half* Bgb = B + (size_t)n0 * K;

    auto fill = [&](int s, int kc) {
        uint32_t base = ab + s * TSTAGE;
        const __half* Agp = Agb + kc * 64;
        const __half* Bgp = Bgb + kc * 64;
        #pragma unroll
        for (int it = 0; it < 4; ++it) {
            int idx = it * 256 + tid;
            int r = idx >> 3, ch = idx & 7;
            cpa16(base + SMEM_SWIZZLE_128B(r * 128 + ch * 16),
                  Agp + (size_t)r * K + ch * 8);
        }
        #pragma unroll
        for (int it = 0; it < 8; ++it) {
            int idx = it * 256 + tid;
            int r = idx >> 3, ch = idx & 7;
            cpa16(base + TAB + SMEM_SWIZZLE_128B(r * 128 + ch * 16),
                  Bgp + (size_t)r * K + ch * 8);
        }
        CP_COMMIT();
    };

    fill(0, 0); fill(1, 1); fill(2, 2);

    const uint32_t idesc = (1u << 4) | (32u << 17) | (8u << 24);  // F32,f16,N=256,M=128
    int ph[4] = {0, 0, 0, 0};

    for (int ks = 0; ks < nk; ++ks) {
        const int s = ks & 3;
        CP_WAIT(2);
        __syncthreads();

        if (tid == 0) {
            asm volatile("fence.proxy.async.shared::cta;" ::: "memory");
            uint32_t base = ab + s * TSTAGE;
            uint64_t ad = mk_desc(base);
            uint64_t bd = mk_desc(base + TAB);
            #pragma unroll
            for (int sub = 0; sub < 4; ++sub)
                mma_f16_ss_cg1(tmem, ad + sub * 2, bd + sub * 2, idesc,
                               (ks > 0) || (sub > 0));
            tc_commit(mbs0 + 8 * s);
        }

        if (ks + 3 < nk) {
            const int nxt = (ks + 3) & 3;
            if (ks >= 1) {
                mbar_wait(mbs0 + 8 * nxt, ph[nxt]);
                ph[nxt] ^= 1;
            }
            fill(nxt, ks + 3);
        } else {
            CP_COMMIT();
        }
    }

    {
        const int sl = (nk - 1) & 3;
        mbar_wait(mbs0 + 8 * sl, ph[sl]);
    }
    asm volatile("tcgen05.fence::after_thread_sync;" ::: "memory");
    __syncthreads();

    // Epilogue: warps 0-3 read D (128 lanes x 256 cols).
    const int w = tid >> 5, lane = tid & 31;
    if (w < 4) {
        const int row = m0 + w * 32 + lane;
        if (MODE == 0) {
            #pragma unroll
            for (int chunk = 0; chunk < 8; ++chunk) {
                uint32_t dr[32];
                LDTM_X32(dr, tmem + chunk * 32);
                asm volatile("tcgen05.wait::ld.sync.aligned;" ::: "memory");
                const int col0 = n0 + chunk * 32;
                float* Crow = C + (size_t)row * N + col0;
                #pragma unroll
                for (int j = 0; j < 32; j += 4) {
                    float4 v = make_float4(__uint_as_float(dr[j])   + bias[col0 + j],
                                           __uint_as_float(dr[j+1]) + bias[col0 + j + 1],
                                           __uint_as_float(dr[j+2]) + bias[col0 + j + 2],
                                           __uint_as_float(dr[j+3]) + bias[col0 + j + 3]);
                    *(float4*)(Crow + j) = v;
                }
            }
        } else {
            const int part = n0 / CM;
            const int head0 = (n0 % CM) >> 7;
            const int b = row >> 11, tok = row & (NTOK - 1);
            if (part == 2) {
                // v: bias -> fp16, layout [B,H,N,D]
                #pragma unroll
                for (int chunk = 0; chunk < 8; ++chunk) {
                    uint32_t dr[32];
                    LDTM_X32(dr, tmem + chunk * 32);
                    asm volatile("tcgen05.wait::ld.sync.aligned;" ::: "memory");
                    const int col0 = n0 + chunk * 32;
                    const int head = head0 + (chunk >> 2), d0 = (chunk & 3) * 32;
                    __half* dst = g_v16 +
                        (((size_t)b * HEADS + head) * NTOK + tok) * DHEAD + d0;
                    #pragma unroll
                    for (int j = 0; j < 32; j += 2)
                        *(__half2*)(dst + j) = __floats2half2_rn(
                            __uint_as_float(dr[j])   + bias[col0 + j],
                            __uint_as_float(dr[j+1]) + bias[col0 + j + 1]);
                }
            } else {
                // q/k: fused bias + RMSNorm + RoPE -> fp16 (q pre-scaled)
                const float* ws = (part == 0) ? wsm : wsm + 128;
                const float sc = (part == 0) ? 0.08838834764831845f : 1.0f;
                __half* dstb = (part == 0) ? g_q16 : g_k16;
                #pragma unroll
                for (int hh = 0; hh < 2; ++hh) {
                    float x[128];
                    #pragma unroll
                    for (int c4 = 0; c4 < 4; ++c4) {
                        uint32_t* xr = (uint32_t*)&x[c4 * 32];
                        LDTM_X32(xr, tmem + (hh * 4 + c4) * 32);
                        asm volatile("tcgen05.wait::ld.sync.aligned;" ::: "memory");
                        const int col0 = n0 + (hh * 4 + c4) * 32;
                        #pragma unroll
                        for (int j = 0; j < 32; ++j)
                            x[c4 * 32 + j] = __uint_as_float(xr[j]) + bias[col0 + j];
                    }
                    float ss = 0.f;
                    #pragma unroll
                    for (int j = 0; j < 128; ++j) ss += x[j] * x[j];
                    const float rn = rsqrtf(ss * (1.f / DHEAD) + 1e-6f);
                    __half* dst = dstb +
                        (((size_t)b * HEADS + head0 + hh) * NTOK + tok) * DHEAD;
                    const float2* rt = g_rtab + (size_t)tok * 64;
                    #pragma unroll
                    for (int p = 0; p < 64; ++p) {
                        float2 t = rt[p];
                        float y0 = x[2*p]     * rn * ws[2*p];
                        float y1 = x[2*p + 1] * rn * ws[2*p + 1];
                        float o0 = (y0 * t.x - y1 * t.y) * sc;
                        float o1 = (y1 * t.x + y0 * t.y) * sc;
                        *(__half2*)(dst + 2*p) = __floats2half2_rn(o0, o1);
                    }
                }
            }
        }
    }
    __syncthreads();
    if (tid < 32) {
        asm volatile("tcgen05.relinquish_alloc_permit.cta_group::1.sync.aligned;");
        asm volatile("tcgen05.dealloc.cta_group::1.sync.aligned.b32 %0, %1;"
                     :: "r"(tmem), "r"(256u));
    }

#else
    // -------- mma.sync fallback (compile-validity only on non-'a' passes;
    //          MODE 1 lacks the rope fusion and is NOT runtime-correct) -----
    __half* sh = (__half*)ts;
    const int lane = tid & 31, warp = tid >> 5;
    const int g = lane >> 2, cq = lane & 3;
    const int wm = warp >> 2, wn = warp & 3;
    const int GST = 128 * 40, GSTG = 2 * GST;

    for (int half = 0; half < 2; ++half) {
        const int nh0 = n0 + half * 128;
        const int lrow = tid >> 2, lch = tid & 3;
        const __half* Ag = A + (size_t)(m0 + lrow) * K + lch * 8;
        const __half* Bg = B + (size_t)(nh0 + lrow) * K + lch * 8;

        float acc[4][4][4] = {};

        auto issue = [&](int s, int k0) {
            __half* As = sh + s * GSTG;
            __half* Bs = As + GST;
            uint32_t da = smaddr(As + lrow * 40 + lch * 8);
            uint32_t db = smaddr(Bs + lrow * 40 + lch * 8);
            cpa16(da,            Ag + k0);
            cpa16(da + 64*40*2,  Ag + (size_t)64 * K + k0);
            cpa16(db,            Bg + k0);
            cpa16(db + 64*40*2,  Bg + (size_t)64 * K + k0);
        };

        issue(0, 0);  CP_COMMIT();
        issue(1, 32); CP_COMMIT();
        issue(2, 64); CP_COMMIT();

        const int nk32 = K / 32;
        for (int ks = 0; ks < nk32; ++ks) {
            if (ks == nk32 - 1) { CP_WAIT(0); } else { CP_WAIT(1); }
            __syncthreads();
            if (ks + 3 < nk32) issue((ks + 3) & 3, (ks + 3) * 32);
            CP_COMMIT();

            const __half* As = sh + (ks & 3) * GSTG;
            const __half* Bs = As + GST;
            #pragma unroll
            for (int kk = 0; kk < 2; ++kk) {
                uint32_t af[4][4], bf[4][2];
                #pragma unroll
                for (int mt = 0; mt < 4; ++mt)
                    ldsm4(af[mt][0], af[mt][1], af[mt][2], af[mt][3],
                          smaddr(As + (wm*64 + mt*16 + (lane & 15)) * 40
                                    + kk*16 + (lane >> 4) * 8));
                #pragma unroll
                for (int p = 0; p < 2; ++p)
                    ldsm4(bf[2*p][0], bf[2*p+1][0], bf[2*p][1], bf[2*p+1][1],
                          smaddr(Bs + (wn*32 + p*16 + (lane & 15)) * 40
                                    + kk*16 + (lane >> 4) * 8));
                #pragma unroll
                for (int mt = 0; mt < 4; ++mt)
                    #pragma unroll
                    for (int nt = 0; nt < 4; ++nt)
                        mma16(acc[mt][nt], af[mt], bf[nt]);
            }
            __syncthreads();
        }

        #pragma unroll
        for (int mt = 0; mt < 4; ++mt) {
            int r0 = m0 + wm*64 + mt*16 + g;
            int r1 = r0 + 8;
            #pragma unroll
            for (int nt = 0; nt < 4; ++nt) {
                int col = nh0 + wn*32 + nt*8 + 2*cq;
                float b0 = bias[col], b1 = bias[col + 1];
                float2 v0 = make_float2(acc[mt][nt][0] + b0, acc[mt][nt][1] + b1);
                float2 v1 = make_float2(acc[mt][nt][2] + b0, acc[mt][nt][3] + b1);
                if (MODE == 0) {
                    *(float2*)(C + (size_t)r0 * N + col) = v0;
                    *(float2*)(C + (size_t)r1 * N + col) = v1;
                } else {
                    int part = col / CM;
                    int within = col % CM;
                    int head = within >> 7;
                    int d = within & 127;
                    int b0i = r0 >> 11, t0 = r0 & (NTOK - 1);
                    int b1i = r1 >> 11, t1 = r1 & (NTOK - 1);
                    size_t o0 = (((size_t)b0i * HEADS + head) * NTOK + t0) * DHEAD + d;
                    size_t o1 = (((size_t)b1i * HEADS + head) * NTOK + t1) * DHEAD + d;
                    if (part == 0) {
                        *(float2*)(g_q + o0) = v0; *(float2*)(g_q + o1) = v1;
                    } else if (part == 1) {
                        *(float2*)(g_k + o0) = v0; *(float2*)(g_k + o1) = v1;
                    } else {
                        *(__half2*)(g_v16 + o0) = __floats2half2_rn(v0.x, v0.y);
                        *(__half2*)(g_v16 + o1) = __floats2half2_rn(v1.x, v1.y);
                    }
                }
            }
        }
        __syncthreads();
    }
#endif
}

// ---------------------------------------------------------------------------
// Flash attention, fp16 mma.sync. Br=128 (8 warps x 16 rows), Bc=64.
// launch_bounds(256,1): no register cap -> no spills (peak live ~160 regs).
// smem: 2 stages x (K[64][136] + V[64][136]) halves = 69632 B.
// ---------------------------------------------------------------------------
#define FKV 8704                // 64*136 halves
#define FSTG (2 * FKV)

__global__ __launch_bounds__(256, 1)
void flash_h()
{
    extern __shared__ __half fsh[];

    const int tid = threadIdx.x, lane = tid & 31, w = tid >> 5;
    const int g = lane >> 2, cq = lane & 3;
    const int q0 = blockIdx.x * 128;
    const size_t hb = ((size_t)blockIdx.z * HEADS + blockIdx.y) * NTOK * DHEAD;
    const __half* Qg = g_q16 + hb + (size_t)q0 * DHEAD;
    const __half* Kg = g_k16 + hb;
    const __half* Vg = g_v16 + hb;

    {   // stage Q (128 rows x 128 cols) across the stage-0 K+V area
        #pragma unroll
        for (int it = 0; it < 8; ++it) {
            int cid = it * 256 + tid;
            int r = cid >> 4, ch = cid & 15;
            *(uint4*)(fsh + r * 136 + ch * 8) = *(const uint4*)(Qg + r * 128 + ch * 8);
        }
    }
    __syncthreads();
    uint32_t qa[8][4];
    #pragma unroll
    for (int kk = 0; kk < 8; ++kk)
        ldsm4(qa[kk][0], qa[kk][1], qa[kk][2], qa[kk][3],
              smaddr(fsh + (w*16 + (lane & 15)) * 136 + kk*16 + (lane >> 4) * 8));
    __syncthreads();

    auto issueKV = [&](int s, int c0) {
        __half* Kst = fsh + s * FSTG;
        __half* Vst = Kst + FKV;
        const __half* Kp = Kg + (size_t)c0 * DHEAD;
        const __half* Vp = Vg + (size_t)c0 * DHEAD;
        #pragma unroll
        for (int it = 0; it < 4; ++it) {
            int cid = it * 256 + tid;
            int r = cid >> 4, ch = cid & 15;
            cpa16(smaddr(Kst + r * 136 + ch * 8), Kp + r * 128 + ch * 8);
            cpa16(smaddr(Vst + r * 136 + ch * 8), Vp + r * 128 + ch * 8);
        }
    };

    float od[16][4] = {};
    float m0 = -INFINITY, m1 = -INFINITY, l0 = 0.f, l1 = 0.f;

    issueKV(0, 0); CP_COMMIT();

    for (int c = 0; c < NTOK / 64; ++c) {
        if (c + 1 < NTOK / 64) issueKV((c + 1) & 1, (c + 1) * 64);
        CP_COMMIT();
        CP_WAIT(1);
        __syncthreads();

        const __half* Kst = fsh + (c & 1) * FSTG;
        const __half* Vst = Kst + FKV;

        float s[8][4] = {};
        #pragma unroll
        for (int kk = 0; kk < 8; ++kk) {
            uint32_t bf[8][2];
            #pragma unroll
            for (int p = 0; p < 4; ++p)
                ldsm4(bf[2*p][0], bf[2*p+1][0], bf[2*p][1], bf[2*p+1][1],
                      smaddr(Kst + (p*16 + (lane & 15)) * 136
                                 + kk*16 + (lane >> 4) * 8));
            #pragma unroll
            for (int nt = 0; nt < 8; ++nt)
                mma16(s[nt], qa[kk], bf[nt]);
        }

        float cm0 = -INFINITY, cm1 = -INFINITY;
        #pragma unroll
        for (int nt = 0; nt < 8; ++nt) {
            cm0 = fmaxf(cm0, fmaxf(s[nt][0], s[nt][1]));
            cm1 = fmaxf(cm1, fmaxf(s[nt][2], s[nt][3]));
        }
        cm0 = fmaxf(cm0, __shfl_xor_sync(0xffffffffu, cm0, 1));
        cm0 = fmaxf(cm0, __shfl_xor_sync(0xffffffffu, cm0, 2));
        cm1 = fmaxf(cm1, __shfl_xor_sync(0xffffffffu, cm1, 1));
        cm1 = fmaxf(cm1, __shfl_xor_sync(0xffffffffu, cm1, 2));
        float mn0 = fmaxf(m0, cm0), mn1 = fmaxf(m1, cm1);
        float al0 = __expf(m0 - mn0), al1 = __expf(m1 - mn1);
        m0 = mn0; m1 = mn1;

        float rs0 = 0.f, rs1 = 0.f;
        #pragma unroll
        for (int nt = 0; nt < 8; ++nt) {
            s[nt][0] = __expf(s[nt][0] - mn0); rs0 += s[nt][0];
            s[nt][1] = __expf(s[nt][1] - mn0); rs0 += s[nt][1];
            s[nt][2] = __expf(s[nt][2] - mn1); rs1 += s[nt][2];
            s[nt][3] = __expf(s[nt][3] - mn1); rs1 += s[nt][3];
        }
        rs0 += __shfl_xor_sync(0xffffffffu, rs0, 1);
        rs0 += __shfl_xor_sync(0xffffffffu, rs0, 2);
        rs1 += __shfl_xor_sync(0xffffffffu, rs1, 1);
        rs1 += __shfl_xor_sync(0xffffffffu, rs1, 2);
        l0 = l0 * al0 + rs0;
        l1 = l1 * al1 + rs1;

        #pragma unroll
        for (int dt = 0; dt < 16; ++dt) {
            od[dt][0] *= al0; od[dt][1] *= al0;
            od[dt][2] *= al1; od[dt][3] *= al1;
        }

        uint32_t pa[4][4];
        #pragma unroll
        for (int k2 = 0; k2 < 4; ++k2) {
            pa[k2][0] = h2u(s[2*k2][0],   s[2*k2][1]);
            pa[k2][1] = h2u(s[2*k2][2],   s[2*k2][3]);
            pa[k2][2] = h2u(s[2*k2+1][0], s[2*k2+1][1]);
            pa[k2][3] = h2u(s[2*k2+1][2], s[2*k2+1][3]);
        }

        #pragma unroll
        for (int k2 = 0; k2 < 4; ++k2) {
            #pragma unroll
            for (int dp = 0; dp < 8; ++dp) {
                uint32_t v0, v1, v2, v3;
                int t = lane >> 3, r = lane & 7;
                ldsm4t(v0, v1, v2, v3,
                       smaddr(Vst + (k2*16 + (t & 1)*8 + r) * 136
                                  + dp*16 + (t >> 1)*8));
                uint32_t b0[2] = {v0, v1}, b1[2] = {v2, v3};
                mma16(od[2*dp],     pa[k2], b0);
                mma16(od[2*dp + 1], pa[k2], b1);
            }
        }
        __syncthreads();
    }

    float inv0 = 1.f / l0, inv1 = 1.f / l1;
    int r0 = q0 + w*16 + g, r1 = r0 + 8;
    size_t base0 = (((size_t)blockIdx.z * NTOK + r0) * HEADS + blockIdx.y) * DHEAD;
    size_t base1 = (((size_t)blockIdx.z * NTOK + r1) * HEADS + blockIdx.y) * DHEAD;
    #pragma unroll
    for (int dt = 0; dt < 16; ++dt) {
        int col = dt*8 + 2*cq;
        *(__half2*)(g_att16 + base0 + col) =
            __floats2half2_rn(od[dt][0] * inv0, od[dt][1] * inv0);
        *(__half2*)(g_att16 + base1 + col) =
            __floats2half2_rn(od[dt][2] * inv1, od[dt][3] * inv1);
    }
}

// ---------------------------------------------------------------------------
extern "C" void kernel_launch(void* const* d_in, const int* in_sizes, int n_in,
                              void* d_out, int out_size)
{
    const float* x      = (const float*)d_in[0];
    const float* qkv_w  = (const float*)d_in[1];
    const float* qkv_b  = (const float*)d_in[2];
    const float* qn_w   = (const float*)d_in[3];
    const float* kn_w   = (const float*)d_in[4];
    const float* proj_w = (const float*)d_in[5];
    const float* proj_b = (const float*)d_in[6];
    float* out = (float*)d_out;

    __half *x16, *w16, *pw16, *att16;
    cudaGetSymbolAddress((void**)&x16,   g_x16);
    cudaGetSymbolAddress((void**)&w16,   g_w16);
    cudaGetSymbolAddress((void**)&pw16,  g_pw16);
    cudaGetSymbolAddress((void**)&att16, g_att16);

    // 0) fp32 -> fp16 pre-conversion + RoPE cos/sin table
    f2h_kernel<<<1024, 256>>>((const float4*)x,      (uint4*)x16,  MTOT * CM / 8);
    f2h_kernel<<<2048, 256>>>((const float4*)qkv_w,  (uint4*)w16,  3 * CM * CM / 8);
    f2h_kernel<<<1024, 256>>>((const float4*)proj_w, (uint4*)pw16, CM * CM / 8);
    rope_tab_kernel<<<NTOK, 64>>>();

    cudaFuncSetAttribute(gemm_u<1>, cudaFuncAttributeMaxDynamicSharedMemorySize, GEMM_SMEM);
    cudaFuncSetAttribute(gemm_u<0>, cudaFuncAttributeMaxDynamicSharedMemorySize, GEMM_SMEM);
    const int fsm = 2 * FSTG * (int)sizeof(__half);     // 69632 B
    cudaFuncSetAttribute(flash_h, cudaFuncAttributeMaxDynamicSharedMemorySize, fsm);

    // 1) QKV GEMM with fused bias+RMSNorm+RoPE epilogue -> q16/k16/v16
    gemm_u<1><<<dim3(3 * CM / 256, MTOT / 128), 256, GEMM_SMEM>>>(
        x16, w16, qkv_b, nullptr, 3 * CM, qn_w, kn_w);

    // 2) Flash attention -> fp16 att [B,N,H,D]
    flash_h<<<dim3(NTOK / 128, HEADS, BATCH), 256, fsm>>>();

    // 3) Output projection -> fp32 out
    gemm_u<0><<<dim3(CM / 256, MTOT / 128), 256, GEMM_SMEM>>>(
        att16, pw16, proj_b, out, CM, nullptr, nullptr);
}